// round 1
// baseline (speedup 1.0000x reference)
#include <cuda_runtime.h>
#include <math.h>

#define DIM   4096
#define S_LEN 2048
#define HD    128
#define NH    32
#define NKV   8
#define KVDIM (NKV*HD)   // 1024

// ---------------- scratch (static device globals; no allocations) ----------
__device__ float g_q  [S_LEN * DIM];     // 32 MB  (roped Q, [s][h*128+d])
__device__ float g_k  [S_LEN * KVDIM];   //  8 MB  (roped K)
__device__ float g_v  [S_LEN * KVDIM];   //  8 MB
__device__ float g_att[S_LEN * DIM];     // 32 MB  (attention output)

// ---------------------------------------------------------------------------
// Tiled fp32 GEMM: C[M,N] = A[M,K] @ B[K,N]  (all row-major, dims % tiles == 0)
// BM=BN=128, BK=16, 256 threads, 8x8 per-thread microtile.
// Optional RoPE epilogue: column c belongs to head (c/128), pair index (c%128)/2.
// ---------------------------------------------------------------------------
template<bool ROPE>
__global__ __launch_bounds__(256)
void gemm_kernel(const float* __restrict__ A, const float* __restrict__ B,
                 float* __restrict__ C, int M, int N, int K,
                 const float* __restrict__ fcos, const float* __restrict__ fsin)
{
    const int BM = 128, BN = 128, BK = 16;
    __shared__ float As[BK][132];   // transposed A tile: As[k][m], padded
    __shared__ float Bs[BK][132];   // Bs[k][n], padded

    const int tid = threadIdx.x;
    const int tm  = tid >> 4;       // 0..15
    const int tn  = tid & 15;       // 0..15
    const int rowBase = blockIdx.y * BM;
    const int colBase = blockIdx.x * BN;

    float acc[8][8];
#pragma unroll
    for (int i = 0; i < 8; i++)
#pragma unroll
        for (int j = 0; j < 8; j++) acc[i][j] = 0.0f;

    for (int k0 = 0; k0 < K; k0 += BK) {
        // load A tile (128 x 16), store transposed
#pragma unroll
        for (int it = 0; it < 2; it++) {
            int idx = tid + it * 256;            // 0..511
            int r   = idx >> 2;                  // 0..127
            int c4  = (idx & 3) * 4;             // 0,4,8,12
            float4 v = *(const float4*)&A[(size_t)(rowBase + r) * K + k0 + c4];
            As[c4 + 0][r] = v.x;
            As[c4 + 1][r] = v.y;
            As[c4 + 2][r] = v.z;
            As[c4 + 3][r] = v.w;
        }
        // load B tile (16 x 128)
#pragma unroll
        for (int it = 0; it < 2; it++) {
            int idx = tid + it * 256;            // 0..511
            int r   = idx >> 5;                  // 0..15
            int c4  = (idx & 31) * 4;            // 0..124
            *(float4*)&Bs[r][c4] =
                *(const float4*)&B[(size_t)(k0 + r) * N + colBase + c4];
        }
        __syncthreads();

#pragma unroll
        for (int kk = 0; kk < BK; kk++) {
            float ra[8], rb[8];
            *(float4*)&ra[0] = *(const float4*)&As[kk][tm * 8];
            *(float4*)&ra[4] = *(const float4*)&As[kk][tm * 8 + 4];
            *(float4*)&rb[0] = *(const float4*)&Bs[kk][tn * 8];
            *(float4*)&rb[4] = *(const float4*)&Bs[kk][tn * 8 + 4];
#pragma unroll
            for (int i = 0; i < 8; i++)
#pragma unroll
                for (int j = 0; j < 8; j++)
                    acc[i][j] += ra[i] * rb[j];
        }
        __syncthreads();
    }

    // epilogue
#pragma unroll
    for (int i = 0; i < 8; i++) {
        int gr = rowBase + tm * 8 + i;
        int gc = colBase + tn * 8;              // even, pairs stay inside thread
        if (ROPE) {
            float out[8];
#pragma unroll
            for (int j = 0; j < 4; j++) {
                int c = gc + 2 * j;
                int d = c & (HD - 1);           // c % 128
                float fc = fcos[gr * (HD / 2) + (d >> 1)];
                float fs = fsin[gr * (HD / 2) + (d >> 1)];
                float e = acc[i][2 * j], o = acc[i][2 * j + 1];
                out[2 * j]     = e * fc - o * fs;
                out[2 * j + 1] = e * fs + o * fc;
            }
            *(float4*)&C[(size_t)gr * N + gc]     = make_float4(out[0], out[1], out[2], out[3]);
            *(float4*)&C[(size_t)gr * N + gc + 4] = make_float4(out[4], out[5], out[6], out[7]);
        } else {
            *(float4*)&C[(size_t)gr * N + gc]     = make_float4(acc[i][0], acc[i][1], acc[i][2], acc[i][3]);
            *(float4*)&C[(size_t)gr * N + gc + 4] = make_float4(acc[i][4], acc[i][5], acc[i][6], acc[i][7]);
        }
    }
}

// ---------------------------------------------------------------------------
// Flash attention (fp32, causal, GQA 4:1).
// Grid: (S/64 q-tiles, 32 heads). 256 threads.
// Phase A (QK^T): 16x16 thread grid, 4x4 scores each -> smem S tile.
// Phase B (softmax+PV): thread (row=tid/4, qd=tid%4) owns 32 contiguous d cols.
// exp() computed exactly once per score (stored back into S tile as p).
// ---------------------------------------------------------------------------
#define FLASH_SMEM_FLOATS (3 * 64 * 132 + 64 * 68)
#define FLASH_SMEM_BYTES  (FLASH_SMEM_FLOATS * 4)

__global__ __launch_bounds__(256)
void flash_kernel(const float* __restrict__ q, const float* __restrict__ k,
                  const float* __restrict__ v, float* __restrict__ out)
{
    extern __shared__ float sm[];
    float* Qs = sm;                   // 64 x 132
    float* Ks = Qs + 64 * 132;        // 64 x 132
    float* Vs = Ks + 64 * 132;        // 64 x 132
    float* Ss = Vs + 64 * 132;        // 64 x 68

    const int tid  = threadIdx.x;
    const int qt   = blockIdx.x;
    const int head = blockIdx.y;
    const int kvh  = head >> 2;       // GQA: 4 q-heads per kv head
    const int qbase = qt * 64;
    const float scale = 0.08838834764831844f;   // 1/sqrt(128)

    // load Q tile (scaled)
#pragma unroll
    for (int it = 0; it < 8; it++) {
        int idx = tid + it * 256;     // 0..2047
        int r   = idx >> 5;           // 0..63
        int c4  = (idx & 31) * 4;
        float4 val = *(const float4*)&q[(size_t)(qbase + r) * DIM + head * HD + c4];
        val.x *= scale; val.y *= scale; val.z *= scale; val.w *= scale;
        *(float4*)&Qs[r * 132 + c4] = val;
    }

    const int row = tid >> 2;         // 0..63
    const int qd  = tid & 3;          // 0..3, owns d in [qd*32, qd*32+32)
    const int tm  = tid >> 4;         // QK phase
    const int tn  = tid & 15;

    float acc[32];
#pragma unroll
    for (int d = 0; d < 32; d++) acc[d] = 0.0f;
    float mrow = -INFINITY, lrow = 0.0f;

    for (int kt = 0; kt <= qt; kt++) {
        const int kbase = kt * 64;
        __syncthreads();  // Qs ready (first iter) / prev-iter Ks,Vs,Ss consumed
#pragma unroll
        for (int it = 0; it < 8; it++) {
            int idx = tid + it * 256;
            int r   = idx >> 5;
            int c4  = (idx & 31) * 4;
            *(float4*)&Ks[r * 132 + c4] =
                *(const float4*)&k[(size_t)(kbase + r) * KVDIM + kvh * HD + c4];
            *(float4*)&Vs[r * 132 + c4] =
                *(const float4*)&v[(size_t)(kbase + r) * KVDIM + kvh * HD + c4];
        }
        __syncthreads();

        // --- QK^T: 4x4 scores per thread ---
        float sc[4][4];
#pragma unroll
        for (int i = 0; i < 4; i++)
#pragma unroll
            for (int j = 0; j < 4; j++) sc[i][j] = 0.0f;

        for (int kk = 0; kk < HD; kk += 4) {
            float4 aq[4], ak[4];
#pragma unroll
            for (int i = 0; i < 4; i++) aq[i] = *(const float4*)&Qs[(tm * 4 + i) * 132 + kk];
#pragma unroll
            for (int j = 0; j < 4; j++) ak[j] = *(const float4*)&Ks[(tn * 4 + j) * 132 + kk];
#pragma unroll
            for (int i = 0; i < 4; i++)
#pragma unroll
                for (int j = 0; j < 4; j++)
                    sc[i][j] += aq[i].x * ak[j].x + aq[i].y * ak[j].y
                              + aq[i].z * ak[j].z + aq[i].w * ak[j].w;
        }
        // causal mask + write to smem
#pragma unroll
        for (int i = 0; i < 4; i++) {
            int gq = qbase + tm * 4 + i;
#pragma unroll
            for (int j = 0; j < 4; j++) {
                int gk = kbase + tn * 4 + j;
                Ss[(tm * 4 + i) * 68 + tn * 4 + j] = (gk <= gq) ? sc[i][j] : -INFINITY;
            }
        }
        __syncthreads();

        // --- online softmax (4 threads per row, quarter each) ---
        float mloc = -INFINITY;
#pragma unroll
        for (int j = 0; j < 16; j++)
            mloc = fmaxf(mloc, Ss[row * 68 + qd * 16 + j]);
        mloc = fmaxf(mloc, __shfl_xor_sync(0xffffffffu, mloc, 1));
        mloc = fmaxf(mloc, __shfl_xor_sync(0xffffffffu, mloc, 2));

        float mnew  = fmaxf(mrow, mloc);
        float alpha = __expf(mrow - mnew);
        float lloc  = 0.0f;
#pragma unroll
        for (int j = 0; j < 16; j++) {
            float p = __expf(Ss[row * 68 + qd * 16 + j] - mnew);
            Ss[row * 68 + qd * 16 + j] = p;
            lloc += p;
        }
        lloc += __shfl_xor_sync(0xffffffffu, lloc, 1);
        lloc += __shfl_xor_sync(0xffffffffu, lloc, 2);
        lrow = lrow * alpha + lloc;
        mrow = mnew;
#pragma unroll
        for (int d = 0; d < 32; d++) acc[d] *= alpha;
        __syncwarp();   // p-values from the other 3 lanes of this row visible

        // --- P @ V for owned 32 d-columns ---
        for (int j = 0; j < 64; j++) {
            float p = Ss[row * 68 + j];
#pragma unroll
            for (int d4 = 0; d4 < 8; d4++) {
                float4 vv = *(const float4*)&Vs[j * 132 + qd * 32 + d4 * 4];
                acc[d4 * 4 + 0] += p * vv.x;
                acc[d4 * 4 + 1] += p * vv.y;
                acc[d4 * 4 + 2] += p * vv.z;
                acc[d4 * 4 + 3] += p * vv.w;
            }
        }
    }

    float inv = 1.0f / lrow;
    size_t obase = (size_t)(qbase + row) * DIM + head * HD + qd * 32;
#pragma unroll
    for (int d4 = 0; d4 < 8; d4++) {
        *(float4*)&out[obase + d4 * 4] =
            make_float4(acc[d4 * 4 + 0] * inv, acc[d4 * 4 + 1] * inv,
                        acc[d4 * 4 + 2] * inv, acc[d4 * 4 + 3] * inv);
    }
}

// ---------------------------------------------------------------------------
extern "C" void kernel_launch(void* const* d_in, const int* in_sizes, int n_in,
                              void* d_out, int out_size)
{
    const float* x    = (const float*)d_in[0];
    const float* wq   = (const float*)d_in[1];
    const float* wk   = (const float*)d_in[2];
    const float* wv   = (const float*)d_in[3];
    const float* wo   = (const float*)d_in[4];
    const float* fcos = (const float*)d_in[5];
    const float* fsin = (const float*)d_in[6];
    // d_in[7] = mask (causal handled analytically), d_in[8] = start_pos (0)
    float* out = (float*)d_out;

    float *q, *k, *v, *att;
    cudaGetSymbolAddress((void**)&q,   g_q);
    cudaGetSymbolAddress((void**)&k,   g_k);
    cudaGetSymbolAddress((void**)&v,   g_v);
    cudaGetSymbolAddress((void**)&att, g_att);

    cudaFuncSetAttribute(flash_kernel,
                         cudaFuncAttributeMaxDynamicSharedMemorySize,
                         FLASH_SMEM_BYTES);

    dim3 threads(256);

    // Q = rope(x @ wq)
    gemm_kernel<true><<<dim3(DIM / 128, S_LEN / 128), threads>>>(
        x, wq, q, S_LEN, DIM, DIM, fcos, fsin);
    // K = rope(x @ wk)
    gemm_kernel<true><<<dim3(KVDIM / 128, S_LEN / 128), threads>>>(
        x, wk, k, S_LEN, KVDIM, DIM, fcos, fsin);
    // V = x @ wv
    gemm_kernel<false><<<dim3(KVDIM / 128, S_LEN / 128), threads>>>(
        x, wv, v, S_LEN, KVDIM, DIM, nullptr, nullptr);
    // attention
    flash_kernel<<<dim3(S_LEN / 64, NH), threads, FLASH_SMEM_BYTES>>>(q, k, v, att);
    // out = att @ wo
    gemm_kernel<false><<<dim3(DIM / 128, S_LEN / 128), threads>>>(
        att, wo, out, S_LEN, DIM, DIM, nullptr, nullptr);
}

// round 6
// speedup vs baseline: 1.3959x; 1.3959x over previous
#include <cuda_runtime.h>
#include <cuda_bf16.h>
#include <math.h>
#include <stdint.h>

#define DIM   4096
#define S_LEN 2048
#define HD    128
#define NH    32
#define NKV   8
#define KVDIM (NKV*HD)   // 1024
#define KTOT  4096
#define NK    (KTOT/32)  // 128 k-iterations of 32

// ======================= scratch globals ===================================
__device__ __nv_bfloat16 g_xhi [S_LEN * DIM];
__device__ __nv_bfloat16 g_xlo [S_LEN * DIM];
__device__ __nv_bfloat16 g_wqt_hi[DIM * DIM];
__device__ __nv_bfloat16 g_wqt_lo[DIM * DIM];
__device__ __nv_bfloat16 g_wkt_hi[KVDIM * DIM];
__device__ __nv_bfloat16 g_wkt_lo[KVDIM * DIM];
__device__ __nv_bfloat16 g_wvt_hi[KVDIM * DIM];
__device__ __nv_bfloat16 g_wvt_lo[KVDIM * DIM];
__device__ __nv_bfloat16 g_wot_hi[DIM * DIM];
__device__ __nv_bfloat16 g_wot_lo[DIM * DIM];
__device__ float g_q  [S_LEN * DIM];
__device__ float g_k  [S_LEN * KVDIM];
__device__ float g_v  [S_LEN * KVDIM];
__device__ float g_att[S_LEN * DIM];
__device__ __nv_bfloat16 g_atthi[S_LEN * DIM];
__device__ __nv_bfloat16 g_attlo[S_LEN * DIM];

// ======================= asm helpers (sm_100-safe) =========================
__device__ __forceinline__ uint32_t smem_u32(const void* p) {
    uint32_t a;
    asm("{ .reg .u64 t; cvta.to.shared.u64 t, %1; cvt.u32.u64 %0, t; }"
        : "=r"(a) : "l"(p));
    return a;
}
#define CP_ASYNC16(dst, src) \
    asm volatile("cp.async.cg.shared.global [%0], [%1], 16;" :: "r"(dst), "l"(src))
#define CP_COMMIT()  asm volatile("cp.async.commit_group;" ::: "memory")
#define CP_WAIT0()   asm volatile("cp.async.wait_group 0;"  ::: "memory")

__device__ __forceinline__ void ldsm_x4(uint32_t* r, uint32_t addr) {
    asm volatile("ldmatrix.sync.aligned.m8n8.x4.shared.b16 {%0,%1,%2,%3}, [%4];"
                 : "=r"(r[0]), "=r"(r[1]), "=r"(r[2]), "=r"(r[3]) : "r"(addr));
}
__device__ __forceinline__ void ldsm_x2(uint32_t* r, uint32_t addr) {
    asm volatile("ldmatrix.sync.aligned.m8n8.x2.shared.b16 {%0,%1}, [%2];"
                 : "=r"(r[0]), "=r"(r[1]) : "r"(addr));
}
__device__ __forceinline__ void mma16816(float* c, const uint32_t* a, const uint32_t* b) {
    asm volatile("mma.sync.aligned.m16n8k16.row.col.f32.bf16.bf16.f32 "
                 "{%0,%1,%2,%3}, {%4,%5,%6,%7}, {%8,%9}, {%0,%1,%2,%3};"
                 : "+f"(c[0]), "+f"(c[1]), "+f"(c[2]), "+f"(c[3])
                 : "r"(a[0]), "r"(a[1]), "r"(a[2]), "r"(a[3]), "r"(b[0]), "r"(b[1]));
}

// ======================= conversion kernels ================================
__global__ __launch_bounds__(256)
void split_kernel(const float* __restrict__ in, __nv_bfloat16* __restrict__ hi,
                  __nv_bfloat16* __restrict__ lo, int n4)
{
    int i = blockIdx.x * blockDim.x + threadIdx.x;
    if (i >= n4) return;
    float4 v = ((const float4*)in)[i];
    __nv_bfloat16 h0 = __float2bfloat16(v.x), h1 = __float2bfloat16(v.y);
    __nv_bfloat16 h2 = __float2bfloat16(v.z), h3 = __float2bfloat16(v.w);
    __nv_bfloat16 l0 = __float2bfloat16(v.x - __bfloat162float(h0));
    __nv_bfloat16 l1 = __float2bfloat16(v.y - __bfloat162float(h1));
    __nv_bfloat16 l2 = __float2bfloat16(v.z - __bfloat162float(h2));
    __nv_bfloat16 l3 = __float2bfloat16(v.w - __bfloat162float(h3));
    ushort4 hv = make_ushort4(*(unsigned short*)&h0, *(unsigned short*)&h1,
                              *(unsigned short*)&h2, *(unsigned short*)&h3);
    ushort4 lv = make_ushort4(*(unsigned short*)&l0, *(unsigned short*)&l1,
                              *(unsigned short*)&l2, *(unsigned short*)&l3);
    ((ushort4*)hi)[i] = hv;
    ((ushort4*)lo)[i] = lv;
}

// W[K][N] fp32 -> Thi/Tlo[N][K] bf16 (transpose + split)
__global__ __launch_bounds__(256)
void transpose_split_kernel(const float* __restrict__ W, __nv_bfloat16* __restrict__ Thi,
                            __nv_bfloat16* __restrict__ Tlo, int K, int N)
{
    __shared__ float t[32][33];
    int n0 = blockIdx.x * 32, k0 = blockIdx.y * 32;
    int tx = threadIdx.x & 31, ty = threadIdx.x >> 5;   // 32 x 8
#pragma unroll
    for (int i = 0; i < 4; i++)
        t[ty + i * 8][tx] = W[(size_t)(k0 + ty + i * 8) * N + n0 + tx];
    __syncthreads();
#pragma unroll
    for (int i = 0; i < 4; i++) {
        float a = t[tx][ty + i * 8];
        __nv_bfloat16 h = __float2bfloat16(a);
        __nv_bfloat16 l = __float2bfloat16(a - __bfloat162float(h));
        size_t o = (size_t)(n0 + ty + i * 8) * K + k0 + tx;
        Thi[o] = h; Tlo[o] = l;
    }
}

// ======================= mma.sync GEMM =====================================
// C[M,N] = (Ahi+Alo)[M,K] @ (Bhi+Blo)[N,K]^T  (3-product split-bf16, fp32 acc)
// BM=BN=128, BK=32, 256 thr, warps 4x2, warp tile 32x64, cp.async dbl-buffer.
// smem: As[2buf][2split][128][40]bf16 (10240B each), Bs same after 40960.
#define GEMM_SMEM_BYTES 81920

template<bool ROPE>
__global__ __launch_bounds__(256, 2)
void gemm_mma(const __nv_bfloat16* __restrict__ Ahi, const __nv_bfloat16* __restrict__ Alo,
              const __nv_bfloat16* __restrict__ Bhi, const __nv_bfloat16* __restrict__ Blo,
              float* __restrict__ C, int N,
              const float* __restrict__ fcos, const float* __restrict__ fsin)
{
    extern __shared__ char smem[];
    const uint32_t sbase = smem_u32(smem);
    const int tid  = threadIdx.x;
    const int lane = tid & 31;
    const int wid  = tid >> 5;
    const int wm   = wid & 3;        // 4 warps over M (32 rows each)
    const int wn   = wid >> 2;       // 2 warps over N (64 cols each)
    const int rowBase = blockIdx.y * 128;
    const int colBase = blockIdx.x * 128;

    // ---- prefetch one k-stage (A:2 splits, B:2 splits; 512 x 16B each) ----
    auto prefetch = [&](int buf, int k0) {
#pragma unroll
        for (int s = 0; s < 2; s++) {
            const __nv_bfloat16* srcA = s ? Alo : Ahi;
            const __nv_bfloat16* srcB = s ? Blo : Bhi;
            uint32_t aB = sbase + (uint32_t)(buf * 2 + s) * 10240u;
            uint32_t bB = aB + 40960u;
#pragma unroll
            for (int c = 0; c < 2; c++) {
                int ch  = tid + c * 256;         // 0..511
                int row = ch >> 2;               // 0..127
                int kc  = (ch & 3) * 8;          // 0,8,16,24
                CP_ASYNC16(aB + (uint32_t)(row * 40 + kc) * 2,
                           srcA + (size_t)(rowBase + row) * KTOT + k0 + kc);
                CP_ASYNC16(bB + (uint32_t)(row * 40 + kc) * 2,
                           srcB + (size_t)(colBase + row) * KTOT + k0 + kc);
            }
        }
        CP_COMMIT();
    };

    float acc[2][8][4];
#pragma unroll
    for (int mi = 0; mi < 2; mi++)
#pragma unroll
        for (int ni = 0; ni < 8; ni++)
#pragma unroll
            for (int r = 0; r < 4; r++) acc[mi][ni][r] = 0.0f;

    // ldmatrix lane address components
    const int am = (lane & 7) + ((lane >> 3) & 1) * 8;   // A x4: row within m16
    const int ak = (lane >> 4) * 8;                      // A x4: k offset
    const int bn = lane & 7;                             // B x2: row within n8
    const int bk = ((lane >> 3) & 1) * 8;                // B x2: k offset

    prefetch(0, 0);

    for (int i = 0; i < NK; i++) {
        CP_WAIT0();
        __syncthreads();
        if (i + 1 < NK) prefetch((i + 1) & 1, (i + 1) * 32);

        const int buf = i & 1;
        const uint32_t aHiB = sbase + (uint32_t)(buf * 2 + 0) * 10240u;
        const uint32_t aLoB = sbase + (uint32_t)(buf * 2 + 1) * 10240u;
        const uint32_t bHiB = aHiB + 40960u;
        const uint32_t bLoB = aLoB + 40960u;

#pragma unroll
        for (int ks = 0; ks < 32; ks += 16) {
            uint32_t aHi[2][4], aLo[2][4];
#pragma unroll
            for (int mi = 0; mi < 2; mi++) {
                uint32_t off = (uint32_t)((wm * 32 + mi * 16 + am) * 40 + ks + ak) * 2;
                ldsm_x4(aHi[mi], aHiB + off);
                ldsm_x4(aLo[mi], aLoB + off);
            }
            uint32_t bf[8][2];
#pragma unroll
            for (int ni = 0; ni < 8; ni++) {
                uint32_t off = (uint32_t)((wn * 64 + ni * 8 + bn) * 40 + ks + bk) * 2;
                ldsm_x2(bf[ni], bHiB + off);
            }
#pragma unroll
            for (int mi = 0; mi < 2; mi++)
#pragma unroll
                for (int ni = 0; ni < 8; ni++) {
                    mma16816(acc[mi][ni], aHi[mi], bf[ni]);   // Ahi*Bhi
                    mma16816(acc[mi][ni], aLo[mi], bf[ni]);   // Alo*Bhi
                }
#pragma unroll
            for (int ni = 0; ni < 8; ni++) {
                uint32_t off = (uint32_t)((wn * 64 + ni * 8 + bn) * 40 + ks + bk) * 2;
                ldsm_x2(bf[ni], bLoB + off);
            }
#pragma unroll
            for (int mi = 0; mi < 2; mi++)
#pragma unroll
                for (int ni = 0; ni < 8; ni++)
                    mma16816(acc[mi][ni], aHi[mi], bf[ni]);   // Ahi*Blo
        }
        __syncthreads();
    }

    // ---- epilogue: acc layout = (row qrow|+8, n-pair qcol) -> RoPE + STG --
    const int qrow = lane >> 2;
    const int qcol = (lane & 3) * 2;
#pragma unroll
    for (int mi = 0; mi < 2; mi++) {
#pragma unroll
        for (int half = 0; half < 2; half++) {
            int r = rowBase + wm * 32 + mi * 16 + qrow + half * 8;
#pragma unroll
            for (int ni = 0; ni < 8; ni++) {
                int n_g = colBase + wn * 64 + ni * 8 + qcol;
                float c0 = acc[mi][ni][half * 2];
                float c1 = acc[mi][ni][half * 2 + 1];
                float2 o;
                if (ROPE) {
                    int d = (n_g & (HD - 1)) >> 1;
                    float fc = fcos[r * (HD / 2) + d];
                    float fs = fsin[r * (HD / 2) + d];
                    o.x = c0 * fc - c1 * fs;
                    o.y = c0 * fs + c1 * fc;
                } else {
                    o.x = c0; o.y = c1;
                }
                *(float2*)&C[(size_t)r * N + n_g] = o;
            }
        }
    }
}

// ======================= flash attention (fp32) ============================
#define FLASH_SMEM_FLOATS (3 * 64 * 132 + 64 * 68)
#define FLASH_SMEM_BYTES  (FLASH_SMEM_FLOATS * 4)

__global__ __launch_bounds__(256)
void flash_kernel(const float* __restrict__ q, const float* __restrict__ k,
                  const float* __restrict__ v, float* __restrict__ out)
{
    extern __shared__ float sm[];
    float* Qs = sm;
    float* Ks = Qs + 64 * 132;
    float* Vs = Ks + 64 * 132;
    float* Ss = Vs + 64 * 132;

    const int tid  = threadIdx.x;
    const int qt   = blockIdx.x;
    const int head = blockIdx.y;
    const int kvh  = head >> 2;
    const int qbase = qt * 64;
    const float scale = 0.08838834764831844f;

#pragma unroll
    for (int it = 0; it < 8; it++) {
        int idx = tid + it * 256;
        int r   = idx >> 5;
        int c4  = (idx & 31) * 4;
        float4 val = *(const float4*)&q[(size_t)(qbase + r) * DIM + head * HD + c4];
        val.x *= scale; val.y *= scale; val.z *= scale; val.w *= scale;
        *(float4*)&Qs[r * 132 + c4] = val;
    }

    const int row = tid >> 2;
    const int qd  = tid & 3;
    const int tm  = tid >> 4;
    const int tn  = tid & 15;

    float acc[32];
#pragma unroll
    for (int d = 0; d < 32; d++) acc[d] = 0.0f;
    float mrow = -INFINITY, lrow = 0.0f;

    for (int kt = 0; kt <= qt; kt++) {
        const int kbase = kt * 64;
        __syncthreads();
#pragma unroll
        for (int it = 0; it < 8; it++) {
            int idx = tid + it * 256;
            int r   = idx >> 5;
            int c4  = (idx & 31) * 4;
            *(float4*)&Ks[r * 132 + c4] =
                *(const float4*)&k[(size_t)(kbase + r) * KVDIM + kvh * HD + c4];
            *(float4*)&Vs[r * 132 + c4] =
                *(const float4*)&v[(size_t)(kbase + r) * KVDIM + kvh * HD + c4];
        }
        __syncthreads();

        float sc[4][4];
#pragma unroll
        for (int i = 0; i < 4; i++)
#pragma unroll
            for (int j = 0; j < 4; j++) sc[i][j] = 0.0f;

        for (int kk = 0; kk < HD; kk += 4) {
            float4 aq[4], ak4[4];
#pragma unroll
            for (int i = 0; i < 4; i++) aq[i]  = *(const float4*)&Qs[(tm * 4 + i) * 132 + kk];
#pragma unroll
            for (int j = 0; j < 4; j++) ak4[j] = *(const float4*)&Ks[(tn * 4 + j) * 132 + kk];
#pragma unroll
            for (int i = 0; i < 4; i++)
#pragma unroll
                for (int j = 0; j < 4; j++)
                    sc[i][j] += aq[i].x * ak4[j].x + aq[i].y * ak4[j].y
                              + aq[i].z * ak4[j].z + aq[i].w * ak4[j].w;
        }
#pragma unroll
        for (int i = 0; i < 4; i++) {
            int gq = qbase + tm * 4 + i;
#pragma unroll
            for (int j = 0; j < 4; j++) {
                int gk = kbase + tn * 4 + j;
                Ss[(tm * 4 + i) * 68 + tn * 4 + j] = (gk <= gq) ? sc[i][j] : -INFINITY;
            }
        }
        __syncthreads();

        float mloc = -INFINITY;
#pragma unroll
        for (int j = 0; j < 16; j++)
            mloc = fmaxf(mloc, Ss[row * 68 + qd * 16 + j]);
        mloc = fmaxf(mloc, __shfl_xor_sync(0xffffffffu, mloc, 1));
        mloc = fmaxf(mloc, __shfl_xor_sync(0xffffffffu, mloc, 2));

        float mnew  = fmaxf(mrow, mloc);
        float alpha = __expf(mrow - mnew);
        float lloc  = 0.0f;
#pragma unroll
        for (int j = 0; j < 16; j++) {
            float p = __expf(Ss[row * 68 + qd * 16 + j] - mnew);
            Ss[row * 68 + qd * 16 + j] = p;
            lloc += p;
        }
        lloc += __shfl_xor_sync(0xffffffffu, lloc, 1);
        lloc += __shfl_xor_sync(0xffffffffu, lloc, 2);
        lrow = lrow * alpha + lloc;
        mrow = mnew;
#pragma unroll
        for (int d = 0; d < 32; d++) acc[d] *= alpha;
        __syncwarp();

        for (int j = 0; j < 64; j++) {
            float p = Ss[row * 68 + j];
#pragma unroll
            for (int d4 = 0; d4 < 8; d4++) {
                float4 vv = *(const float4*)&Vs[j * 132 + qd * 32 + d4 * 4];
                acc[d4 * 4 + 0] += p * vv.x;
                acc[d4 * 4 + 1] += p * vv.y;
                acc[d4 * 4 + 2] += p * vv.z;
                acc[d4 * 4 + 3] += p * vv.w;
            }
        }
    }

    float inv = 1.0f / lrow;
    size_t obase = (size_t)(qbase + row) * DIM + head * HD + qd * 32;
#pragma unroll
    for (int d4 = 0; d4 < 8; d4++) {
        *(float4*)&out[obase + d4 * 4] =
            make_float4(acc[d4 * 4 + 0] * inv, acc[d4 * 4 + 1] * inv,
                        acc[d4 * 4 + 2] * inv, acc[d4 * 4 + 3] * inv);
    }
}

// ======================= launch ============================================
extern "C" void kernel_launch(void* const* d_in, const int* in_sizes, int n_in,
                              void* d_out, int out_size)
{
    const float* x    = (const float*)d_in[0];
    const float* wq   = (const float*)d_in[1];
    const float* wk   = (const float*)d_in[2];
    const float* wv   = (const float*)d_in[3];
    const float* wo   = (const float*)d_in[4];
    const float* fcos = (const float*)d_in[5];
    const float* fsin = (const float*)d_in[6];
    float* out = (float*)d_out;

    __nv_bfloat16 *xhi, *xlo, *wqth, *wqtl, *wkth, *wktl, *wvth, *wvtl, *woth, *wotl;
    __nv_bfloat16 *atthi, *attlo;
    float *q, *k, *v, *att;
    cudaGetSymbolAddress((void**)&xhi,  g_xhi);
    cudaGetSymbolAddress((void**)&xlo,  g_xlo);
    cudaGetSymbolAddress((void**)&wqth, g_wqt_hi);
    cudaGetSymbolAddress((void**)&wqtl, g_wqt_lo);
    cudaGetSymbolAddress((void**)&wkth, g_wkt_hi);
    cudaGetSymbolAddress((void**)&wktl, g_wkt_lo);
    cudaGetSymbolAddress((void**)&wvth, g_wvt_hi);
    cudaGetSymbolAddress((void**)&wvtl, g_wvt_lo);
    cudaGetSymbolAddress((void**)&woth, g_wot_hi);
    cudaGetSymbolAddress((void**)&wotl, g_wot_lo);
    cudaGetSymbolAddress((void**)&q,    g_q);
    cudaGetSymbolAddress((void**)&k,    g_k);
    cudaGetSymbolAddress((void**)&v,    g_v);
    cudaGetSymbolAddress((void**)&att,  g_att);
    cudaGetSymbolAddress((void**)&atthi,g_atthi);
    cudaGetSymbolAddress((void**)&attlo,g_attlo);

    cudaFuncSetAttribute(gemm_mma<true>,
                         cudaFuncAttributeMaxDynamicSharedMemorySize, GEMM_SMEM_BYTES);
    cudaFuncSetAttribute(gemm_mma<false>,
                         cudaFuncAttributeMaxDynamicSharedMemorySize, GEMM_SMEM_BYTES);
    cudaFuncSetAttribute(flash_kernel,
                         cudaFuncAttributeMaxDynamicSharedMemorySize, FLASH_SMEM_BYTES);

    // --- conversions ---
    int n4x = S_LEN * DIM / 4;
    split_kernel<<<(n4x + 255) / 256, 256>>>(x, xhi, xlo, n4x);
    transpose_split_kernel<<<dim3(DIM / 32,   DIM / 32), 256>>>(wq, wqth, wqtl, DIM, DIM);
    transpose_split_kernel<<<dim3(KVDIM / 32, DIM / 32), 256>>>(wk, wkth, wktl, DIM, KVDIM);
    transpose_split_kernel<<<dim3(KVDIM / 32, DIM / 32), 256>>>(wv, wvth, wvtl, DIM, KVDIM);
    transpose_split_kernel<<<dim3(DIM / 32,   DIM / 32), 256>>>(wo, woth, wotl, DIM, DIM);

    // --- projections (mma.sync) ---
    gemm_mma<true><<<dim3(DIM / 128,   S_LEN / 128), 256, GEMM_SMEM_BYTES>>>(
        xhi, xlo, wqth, wqtl, q, DIM, fcos, fsin);
    gemm_mma<true><<<dim3(KVDIM / 128, S_LEN / 128), 256, GEMM_SMEM_BYTES>>>(
        xhi, xlo, wkth, wktl, k, KVDIM, fcos, fsin);
    gemm_mma<false><<<dim3(KVDIM / 128, S_LEN / 128), 256, GEMM_SMEM_BYTES>>>(
        xhi, xlo, wvth, wvtl, v, KVDIM, nullptr, nullptr);

    // --- attention ---
    flash_kernel<<<dim3(S_LEN / 64, NH), 256, FLASH_SMEM_BYTES>>>(q, k, v, att);

    // --- output projection ---
    split_kernel<<<(n4x + 255) / 256, 256>>>(att, atthi, attlo, n4x);
    gemm_mma<false><<<dim3(DIM / 128, S_LEN / 128), 256, GEMM_SMEM_BYTES>>>(
        atthi, attlo, woth, wotl, out, DIM, nullptr, nullptr);
}

// round 7
// speedup vs baseline: 4.9534x; 3.5486x over previous
#include <cuda_runtime.h>
#include <cuda_bf16.h>
#include <math.h>
#include <stdint.h>

#define DIM   4096
#define S_LEN 2048
#define HD    128
#define NH    32
#define NKV   8
#define KVDIM (NKV*HD)   // 1024
#define KTOT  4096
#define NK    (KTOT/32)  // 128

// ======================= scratch globals ===================================
__device__ __nv_bfloat16 g_xhi [S_LEN * DIM];
__device__ __nv_bfloat16 g_xlo [S_LEN * DIM];
__device__ __nv_bfloat16 g_wqt_hi[DIM * DIM];
__device__ __nv_bfloat16 g_wqt_lo[DIM * DIM];
__device__ __nv_bfloat16 g_wkt_hi[KVDIM * DIM];
__device__ __nv_bfloat16 g_wkt_lo[KVDIM * DIM];
__device__ __nv_bfloat16 g_wvt_hi[KVDIM * DIM];
__device__ __nv_bfloat16 g_wvt_lo[KVDIM * DIM];
__device__ __nv_bfloat16 g_wot_hi[DIM * DIM];
__device__ __nv_bfloat16 g_wot_lo[DIM * DIM];
__device__ __nv_bfloat16 g_qhi [S_LEN * DIM];
__device__ __nv_bfloat16 g_qlo [S_LEN * DIM];
__device__ __nv_bfloat16 g_khi [S_LEN * KVDIM];
__device__ __nv_bfloat16 g_klo [S_LEN * KVDIM];
__device__ __nv_bfloat16 g_vhi [S_LEN * KVDIM];
__device__ __nv_bfloat16 g_vlo [S_LEN * KVDIM];
__device__ __nv_bfloat16 g_atthi[S_LEN * DIM];
__device__ __nv_bfloat16 g_attlo[S_LEN * DIM];

// ======================= asm helpers (sm_100-safe) =========================
__device__ __forceinline__ uint32_t smem_u32(const void* p) {
    uint32_t a;
    asm("{ .reg .u64 t; cvta.to.shared.u64 t, %1; cvt.u32.u64 %0, t; }"
        : "=r"(a) : "l"(p));
    return a;
}
#define CP_ASYNC16(dst, src) \
    asm volatile("cp.async.cg.shared.global [%0], [%1], 16;" :: "r"(dst), "l"(src))
#define CP_COMMIT()  asm volatile("cp.async.commit_group;" ::: "memory")
#define CP_WAIT0()   asm volatile("cp.async.wait_group 0;"  ::: "memory")
#define CP_WAIT1()   asm volatile("cp.async.wait_group 1;"  ::: "memory")

__device__ __forceinline__ void ldsm_x4(uint32_t* r, uint32_t addr) {
    asm volatile("ldmatrix.sync.aligned.m8n8.x4.shared.b16 {%0,%1,%2,%3}, [%4];"
                 : "=r"(r[0]), "=r"(r[1]), "=r"(r[2]), "=r"(r[3]) : "r"(addr));
}
__device__ __forceinline__ void ldsm_x2(uint32_t* r, uint32_t addr) {
    asm volatile("ldmatrix.sync.aligned.m8n8.x2.shared.b16 {%0,%1}, [%2];"
                 : "=r"(r[0]), "=r"(r[1]) : "r"(addr));
}
__device__ __forceinline__ void ldsm_x2t(uint32_t* r, uint32_t addr) {
    asm volatile("ldmatrix.sync.aligned.m8n8.x2.trans.shared.b16 {%0,%1}, [%2];"
                 : "=r"(r[0]), "=r"(r[1]) : "r"(addr));
}
__device__ __forceinline__ void mma16816(float* c, const uint32_t* a, const uint32_t* b) {
    asm volatile("mma.sync.aligned.m16n8k16.row.col.f32.bf16.bf16.f32 "
                 "{%0,%1,%2,%3}, {%4,%5,%6,%7}, {%8,%9}, {%0,%1,%2,%3};"
                 : "+f"(c[0]), "+f"(c[1]), "+f"(c[2]), "+f"(c[3])
                 : "r"(a[0]), "r"(a[1]), "r"(a[2]), "r"(a[3]), "r"(b[0]), "r"(b[1]));
}
__device__ __forceinline__ uint32_t pack_bf16(float a, float b) {
    __nv_bfloat162 h = __floats2bfloat162_rn(a, b);
    return *(uint32_t*)&h;
}

// ======================= conversion kernels ================================
__global__ __launch_bounds__(256)
void split_kernel(const float* __restrict__ in, __nv_bfloat16* __restrict__ hi,
                  __nv_bfloat16* __restrict__ lo, int n4)
{
    int i = blockIdx.x * blockDim.x + threadIdx.x;
    if (i >= n4) return;
    float4 v = ((const float4*)in)[i];
    __nv_bfloat16 h0 = __float2bfloat16(v.x), h1 = __float2bfloat16(v.y);
    __nv_bfloat16 h2 = __float2bfloat16(v.z), h3 = __float2bfloat16(v.w);
    __nv_bfloat16 l0 = __float2bfloat16(v.x - __bfloat162float(h0));
    __nv_bfloat16 l1 = __float2bfloat16(v.y - __bfloat162float(h1));
    __nv_bfloat16 l2 = __float2bfloat16(v.z - __bfloat162float(h2));
    __nv_bfloat16 l3 = __float2bfloat16(v.w - __bfloat162float(h3));
    ushort4 hv = make_ushort4(*(unsigned short*)&h0, *(unsigned short*)&h1,
                              *(unsigned short*)&h2, *(unsigned short*)&h3);
    ushort4 lv = make_ushort4(*(unsigned short*)&l0, *(unsigned short*)&l1,
                              *(unsigned short*)&l2, *(unsigned short*)&l3);
    ((ushort4*)hi)[i] = hv;
    ((ushort4*)lo)[i] = lv;
}

__global__ __launch_bounds__(256)
void transpose_split_kernel(const float* __restrict__ W, __nv_bfloat16* __restrict__ Thi,
                            __nv_bfloat16* __restrict__ Tlo, int K, int N)
{
    __shared__ float t[32][33];
    int n0 = blockIdx.x * 32, k0 = blockIdx.y * 32;
    int tx = threadIdx.x & 31, ty = threadIdx.x >> 5;
#pragma unroll
    for (int i = 0; i < 4; i++)
        t[ty + i * 8][tx] = W[(size_t)(k0 + ty + i * 8) * N + n0 + tx];
    __syncthreads();
#pragma unroll
    for (int i = 0; i < 4; i++) {
        float a = t[tx][ty + i * 8];
        __nv_bfloat16 h = __float2bfloat16(a);
        __nv_bfloat16 l = __float2bfloat16(a - __bfloat162float(h));
        size_t o = (size_t)(n0 + ty + i * 8) * K + k0 + tx;
        Thi[o] = h; Tlo[o] = l;
    }
}

// ======================= mma.sync GEMM =====================================
// BM=BN=128, BK=32, 256 thr, warps 4x2, warp tile 32x64.
// SPLITOUT: write bf16 hi/lo pair outputs instead of fp32.
#define GEMM_SMEM_BYTES 81920

template<bool ROPE, bool SPLITOUT>
__global__ __launch_bounds__(256, 2)
void gemm_mma(const __nv_bfloat16* __restrict__ Ahi, const __nv_bfloat16* __restrict__ Alo,
              const __nv_bfloat16* __restrict__ Bhi, const __nv_bfloat16* __restrict__ Blo,
              float* __restrict__ C,
              __nv_bfloat16* __restrict__ Chi, __nv_bfloat16* __restrict__ Clo,
              int N, const float* __restrict__ fcos, const float* __restrict__ fsin,
              float oscale)
{
    extern __shared__ char smem[];
    const uint32_t sbase = smem_u32(smem);
    const int tid  = threadIdx.x;
    const int lane = tid & 31;
    const int wid  = tid >> 5;
    const int wm   = wid & 3;
    const int wn   = wid >> 2;
    const int rowBase = blockIdx.y * 128;
    const int colBase = blockIdx.x * 128;

    auto prefetch = [&](int buf, int k0) {
#pragma unroll
        for (int s = 0; s < 2; s++) {
            const __nv_bfloat16* srcA = s ? Alo : Ahi;
            const __nv_bfloat16* srcB = s ? Blo : Bhi;
            uint32_t aB = sbase + (uint32_t)(buf * 2 + s) * 10240u;
            uint32_t bB = aB + 40960u;
#pragma unroll
            for (int c = 0; c < 2; c++) {
                int ch  = tid + c * 256;
                int row = ch >> 2;
                int kc  = (ch & 3) * 8;
                CP_ASYNC16(aB + (uint32_t)(row * 40 + kc) * 2,
                           srcA + (size_t)(rowBase + row) * KTOT + k0 + kc);
                CP_ASYNC16(bB + (uint32_t)(row * 40 + kc) * 2,
                           srcB + (size_t)(colBase + row) * KTOT + k0 + kc);
            }
        }
        CP_COMMIT();
    };

    float acc[2][8][4];
#pragma unroll
    for (int mi = 0; mi < 2; mi++)
#pragma unroll
        for (int ni = 0; ni < 8; ni++)
#pragma unroll
            for (int r = 0; r < 4; r++) acc[mi][ni][r] = 0.0f;

    const int am = (lane & 7) + ((lane >> 3) & 1) * 8;
    const int ak = (lane >> 4) * 8;
    const int bn = lane & 7;
    const int bk = ((lane >> 3) & 1) * 8;

    prefetch(0, 0);

    for (int i = 0; i < NK; i++) {
        CP_WAIT0();
        __syncthreads();
        if (i + 1 < NK) prefetch((i + 1) & 1, (i + 1) * 32);

        const int buf = i & 1;
        const uint32_t aHiB = sbase + (uint32_t)(buf * 2 + 0) * 10240u;
        const uint32_t aLoB = sbase + (uint32_t)(buf * 2 + 1) * 10240u;
        const uint32_t bHiB = aHiB + 40960u;
        const uint32_t bLoB = aLoB + 40960u;

#pragma unroll
        for (int ks = 0; ks < 32; ks += 16) {
            uint32_t aHi[2][4], aLo[2][4];
#pragma unroll
            for (int mi = 0; mi < 2; mi++) {
                uint32_t off = (uint32_t)((wm * 32 + mi * 16 + am) * 40 + ks + ak) * 2;
                ldsm_x4(aHi[mi], aHiB + off);
                ldsm_x4(aLo[mi], aLoB + off);
            }
            uint32_t bf[8][2];
#pragma unroll
            for (int ni = 0; ni < 8; ni++) {
                uint32_t off = (uint32_t)((wn * 64 + ni * 8 + bn) * 40 + ks + bk) * 2;
                ldsm_x2(bf[ni], bHiB + off);
            }
#pragma unroll
            for (int mi = 0; mi < 2; mi++)
#pragma unroll
                for (int ni = 0; ni < 8; ni++) {
                    mma16816(acc[mi][ni], aHi[mi], bf[ni]);
                    mma16816(acc[mi][ni], aLo[mi], bf[ni]);
                }
#pragma unroll
            for (int ni = 0; ni < 8; ni++) {
                uint32_t off = (uint32_t)((wn * 64 + ni * 8 + bn) * 40 + ks + bk) * 2;
                ldsm_x2(bf[ni], bLoB + off);
            }
#pragma unroll
            for (int mi = 0; mi < 2; mi++)
#pragma unroll
                for (int ni = 0; ni < 8; ni++)
                    mma16816(acc[mi][ni], aHi[mi], bf[ni]);
        }
        __syncthreads();
    }

    const int qrow = lane >> 2;
    const int qcol = (lane & 3) * 2;
#pragma unroll
    for (int mi = 0; mi < 2; mi++) {
#pragma unroll
        for (int half = 0; half < 2; half++) {
            int r = rowBase + wm * 32 + mi * 16 + qrow + half * 8;
#pragma unroll
            for (int ni = 0; ni < 8; ni++) {
                int n_g = colBase + wn * 64 + ni * 8 + qcol;
                float c0 = acc[mi][ni][half * 2];
                float c1 = acc[mi][ni][half * 2 + 1];
                float ox, oy;
                if (ROPE) {
                    int d = (n_g & (HD - 1)) >> 1;
                    float fc = fcos[r * (HD / 2) + d];
                    float fs = fsin[r * (HD / 2) + d];
                    ox = c0 * fc - c1 * fs;
                    oy = c0 * fs + c1 * fc;
                } else {
                    ox = c0; oy = c1;
                }
                if (SPLITOUT) {
                    ox *= oscale; oy *= oscale;
                    __nv_bfloat16 h0 = __float2bfloat16(ox);
                    __nv_bfloat16 h1 = __float2bfloat16(oy);
                    float l0f = ox - __bfloat162float(h0);
                    float l1f = oy - __bfloat162float(h1);
                    size_t o = (size_t)r * N + n_g;
                    *(uint32_t*)&Chi[o] = pack_bf16(__bfloat162float(h0), __bfloat162float(h1));
                    *(uint32_t*)&Clo[o] = pack_bf16(l0f, l1f);
                } else {
                    *(float2*)&C[(size_t)r * N + n_g] = make_float2(ox, oy);
                }
            }
        }
    }
}

// ======================= flash attention (mma.sync) ========================
// BM=128 q rows (8 warps x m16), BN=64 keys/tile, d=128.
// smem: Qhi[128][136], Qlo; 2 x { Khi[64][136], Klo, Vhi, Vlo }.
#define FPAD 136
#define FQ_BYTES   (128 * FPAD * 2)        // 34816
#define FT_BYTES   (64 * FPAD * 2)         // 17408
#define FKV_BYTES  (4 * FT_BYTES)          // 69632
#define FLASH_SMEM (2 * FQ_BYTES + 2 * FKV_BYTES)   // 208896

__global__ __launch_bounds__(256, 1)
void flash_mma(const __nv_bfloat16* __restrict__ qhi, const __nv_bfloat16* __restrict__ qlo,
               const __nv_bfloat16* __restrict__ khi, const __nv_bfloat16* __restrict__ klo,
               const __nv_bfloat16* __restrict__ vhi, const __nv_bfloat16* __restrict__ vlo,
               __nv_bfloat16* __restrict__ atthi, __nv_bfloat16* __restrict__ attlo)
{
    extern __shared__ char smem[];
    const uint32_t sbase = smem_u32(smem);
    const int tid  = threadIdx.x;
    const int lane = tid & 31;
    const int w    = tid >> 5;           // 8 warps, warp w: q rows w*16..w*16+15
    const int qt   = gridDim.x - 1 - blockIdx.x;   // big tiles first
    const int head = blockIdx.y;
    const int kvh  = head >> 2;
    const int qbase = qt * 128;
    const int ktmax = 2 * qt + 1;

    const uint32_t QHI = sbase;
    const uint32_t QLO = sbase + FQ_BYTES;
    const uint32_t KVB = sbase + 2 * FQ_BYTES;

    // ---- load Q (hi+lo) ----
#pragma unroll
    for (int t = 0; t < 16; t++) {
        int c = tid + t * 256;           // 0..4095
        int arr = c >> 11;               // 0..1
        int rem = c & 2047;
        int row = rem >> 4;
        int ch  = rem & 15;
        const __nv_bfloat16* src = arr ? qlo : qhi;
        uint32_t dst = (arr ? QLO : QHI) + (uint32_t)(row * FPAD + ch * 8) * 2;
        CP_ASYNC16(dst, src + (size_t)(qbase + row) * DIM + head * HD + ch * 8);
    }
    // ---- load KV tile 0 ----
    auto load_kv = [&](int buf, int kt) {
        const int kbase = kt * 64;
        uint32_t base = KVB + (uint32_t)buf * FKV_BYTES;
#pragma unroll
        for (int t = 0; t < 16; t++) {
            int c = tid + t * 256;       // 0..4095
            int arr = c >> 10;           // 0..3
            int rem = c & 1023;
            int row = rem >> 4;
            int ch  = rem & 15;
            const __nv_bfloat16* src = (arr == 0) ? khi : (arr == 1) ? klo
                                     : (arr == 2) ? vhi : vlo;
            uint32_t dst = base + (uint32_t)arr * FT_BYTES + (uint32_t)(row * FPAD + ch * 8) * 2;
            CP_ASYNC16(dst, src + (size_t)(kbase + row) * KVDIM + kvh * HD + ch * 8);
        }
        CP_COMMIT();
    };
    load_kv(0, 0);      // commits Q + tile0 together

    const int am = (lane & 7) + ((lane >> 3) & 1) * 8;
    const int ak = (lane >> 4) * 8;
    const int bn = lane & 7;
    const int bk = ((lane >> 3) & 1) * 8;
    const int vk = lane & 15;
    const int qrow = lane >> 2;
    const int qcol = (lane & 3) * 2;

    float O[16][4];
#pragma unroll
    for (int ni = 0; ni < 16; ni++)
#pragma unroll
        for (int r = 0; r < 4; r++) O[ni][r] = 0.0f;
    float m0 = -1e30f, m1 = -1e30f, l0 = 0.0f, l1 = 0.0f;

    for (int kt = 0; kt <= ktmax; kt++) {
        bool pf = (kt + 1 <= ktmax);
        if (pf) load_kv((kt + 1) & 1, kt + 1);
        if (pf) { CP_WAIT1(); } else { CP_WAIT0(); }
        __syncthreads();

        const uint32_t base = KVB + (uint32_t)(kt & 1) * FKV_BYTES;
        const uint32_t KHI = base, KLO = base + FT_BYTES;
        const uint32_t VHI = base + 2 * FT_BYTES, VLO = base + 3 * FT_BYTES;

        // ---- S = Q K^T (3-product split) ----
        float S[8][4];
#pragma unroll
        for (int j = 0; j < 8; j++)
#pragma unroll
            for (int r = 0; r < 4; r++) S[j][r] = 0.0f;

#pragma unroll
        for (int ks = 0; ks < 8; ks++) {
            uint32_t qh[4], ql[4];
            uint32_t qoff = (uint32_t)((w * 16 + am) * FPAD + ks * 16 + ak) * 2;
            ldsm_x4(qh, QHI + qoff);
            ldsm_x4(ql, QLO + qoff);
#pragma unroll
            for (int j = 0; j < 8; j++) {
                uint32_t kh[2], kl[2];
                uint32_t koff = (uint32_t)((j * 8 + bn) * FPAD + ks * 16 + bk) * 2;
                ldsm_x2(kh, KHI + koff);
                ldsm_x2(kl, KLO + koff);
                mma16816(S[j], qh, kh);
                mma16816(S[j], ql, kh);
                mma16816(S[j], qh, kl);
            }
        }

        // ---- causal mask (only diagonal region) ----
        if (kt >= 2 * qt) {
            const int kbase = kt * 64;
            int gq0 = qbase + w * 16 + qrow;
            int gq1 = gq0 + 8;
#pragma unroll
            for (int j = 0; j < 8; j++) {
                int gk = kbase + j * 8 + qcol;
                if (gk     > gq0) S[j][0] = -1e30f;
                if (gk + 1 > gq0) S[j][1] = -1e30f;
                if (gk     > gq1) S[j][2] = -1e30f;
                if (gk + 1 > gq1) S[j][3] = -1e30f;
            }
        }

        // ---- online softmax ----
        float mx0 = -1e30f, mx1 = -1e30f;
#pragma unroll
        for (int j = 0; j < 8; j++) {
            mx0 = fmaxf(mx0, fmaxf(S[j][0], S[j][1]));
            mx1 = fmaxf(mx1, fmaxf(S[j][2], S[j][3]));
        }
        mx0 = fmaxf(mx0, __shfl_xor_sync(0xffffffffu, mx0, 1));
        mx0 = fmaxf(mx0, __shfl_xor_sync(0xffffffffu, mx0, 2));
        mx1 = fmaxf(mx1, __shfl_xor_sync(0xffffffffu, mx1, 1));
        mx1 = fmaxf(mx1, __shfl_xor_sync(0xffffffffu, mx1, 2));

        float m0n = fmaxf(m0, mx0), m1n = fmaxf(m1, mx1);
        float a0 = __expf(m0 - m0n), a1 = __expf(m1 - m1n);
        float s0 = 0.0f, s1 = 0.0f;
#pragma unroll
        for (int j = 0; j < 8; j++) {
            S[j][0] = __expf(S[j][0] - m0n);
            S[j][1] = __expf(S[j][1] - m0n);
            S[j][2] = __expf(S[j][2] - m1n);
            S[j][3] = __expf(S[j][3] - m1n);
            s0 += S[j][0] + S[j][1];
            s1 += S[j][2] + S[j][3];
        }
        s0 += __shfl_xor_sync(0xffffffffu, s0, 1);
        s0 += __shfl_xor_sync(0xffffffffu, s0, 2);
        s1 += __shfl_xor_sync(0xffffffffu, s1, 1);
        s1 += __shfl_xor_sync(0xffffffffu, s1, 2);
        l0 = l0 * a0 + s0;  m0 = m0n;
        l1 = l1 * a1 + s1;  m1 = m1n;
#pragma unroll
        for (int ni = 0; ni < 16; ni++) {
            O[ni][0] *= a0; O[ni][1] *= a0;
            O[ni][2] *= a1; O[ni][3] *= a1;
        }

        // ---- O += P V (3-product split) ----
#pragma unroll
        for (int kt2 = 0; kt2 < 4; kt2++) {
            uint32_t ph[4], pl[4];
#pragma unroll
            for (int half = 0; half < 2; half++) {
                float p0 = S[2 * kt2 + half][0], p1 = S[2 * kt2 + half][1];
                float p2 = S[2 * kt2 + half][2], p3 = S[2 * kt2 + half][3];
                float h0 = __bfloat162float(__float2bfloat16(p0));
                float h1 = __bfloat162float(__float2bfloat16(p1));
                float h2 = __bfloat162float(__float2bfloat16(p2));
                float h3 = __bfloat162float(__float2bfloat16(p3));
                ph[half * 2 + 0] = pack_bf16(h0, h1);
                ph[half * 2 + 1] = pack_bf16(h2, h3);
                pl[half * 2 + 0] = pack_bf16(p0 - h0, p1 - h1);
                pl[half * 2 + 1] = pack_bf16(p2 - h2, p3 - h3);
            }
            // A-frag order: a0=(r,k..),a1=(r+8,k..),a2=(r,k+8..),a3=(r+8,k+8..)
            uint32_t pa_h[4] = { ph[0], ph[1], ph[2], ph[3] };
            uint32_t pa_l[4] = { pl[0], pl[1], pl[2], pl[3] };
#pragma unroll
            for (int ni = 0; ni < 16; ni++) {
                uint32_t vh[2], vl[2];
                uint32_t voff = (uint32_t)((kt2 * 16 + vk) * FPAD + ni * 8) * 2;
                ldsm_x2t(vh, VHI + voff);
                ldsm_x2t(vl, VLO + voff);
                mma16816(O[ni], pa_h, vh);
                mma16816(O[ni], pa_l, vh);
                mma16816(O[ni], pa_h, vl);
            }
        }
        __syncthreads();
    }

    // ---- epilogue: normalize, split, store ----
    float inv0 = 1.0f / l0, inv1 = 1.0f / l1;
    int gq0 = qbase + w * 16 + qrow;
    int gq1 = gq0 + 8;
#pragma unroll
    for (int ni = 0; ni < 16; ni++) {
        int col = head * HD + ni * 8 + qcol;
        float o0 = O[ni][0] * inv0, o1 = O[ni][1] * inv0;
        float o2 = O[ni][2] * inv1, o3 = O[ni][3] * inv1;
        float h0 = __bfloat162float(__float2bfloat16(o0));
        float h1 = __bfloat162float(__float2bfloat16(o1));
        float h2 = __bfloat162float(__float2bfloat16(o2));
        float h3 = __bfloat162float(__float2bfloat16(o3));
        size_t p0 = (size_t)gq0 * DIM + col;
        size_t p1 = (size_t)gq1 * DIM + col;
        *(uint32_t*)&atthi[p0] = pack_bf16(h0, h1);
        *(uint32_t*)&attlo[p0] = pack_bf16(o0 - h0, o1 - h1);
        *(uint32_t*)&atthi[p1] = pack_bf16(h2, h3);
        *(uint32_t*)&attlo[p1] = pack_bf16(o2 - h2, o3 - h3);
    }
}

// ======================= launch ============================================
extern "C" void kernel_launch(void* const* d_in, const int* in_sizes, int n_in,
                              void* d_out, int out_size)
{
    const float* x    = (const float*)d_in[0];
    const float* wq   = (const float*)d_in[1];
    const float* wk   = (const float*)d_in[2];
    const float* wv   = (const float*)d_in[3];
    const float* wo   = (const float*)d_in[4];
    const float* fcos = (const float*)d_in[5];
    const float* fsin = (const float*)d_in[6];
    float* out = (float*)d_out;

    __nv_bfloat16 *xhi, *xlo, *wqth, *wqtl, *wkth, *wktl, *wvth, *wvtl, *woth, *wotl;
    __nv_bfloat16 *qhi, *qlo, *khi, *klo, *vhi, *vlo, *atthi, *attlo;
    cudaGetSymbolAddress((void**)&xhi,  g_xhi);
    cudaGetSymbolAddress((void**)&xlo,  g_xlo);
    cudaGetSymbolAddress((void**)&wqth, g_wqt_hi);
    cudaGetSymbolAddress((void**)&wqtl, g_wqt_lo);
    cudaGetSymbolAddress((void**)&wkth, g_wkt_hi);
    cudaGetSymbolAddress((void**)&wktl, g_wkt_lo);
    cudaGetSymbolAddress((void**)&wvth, g_wvt_hi);
    cudaGetSymbolAddress((void**)&wvtl, g_wvt_lo);
    cudaGetSymbolAddress((void**)&woth, g_wot_hi);
    cudaGetSymbolAddress((void**)&wotl, g_wot_lo);
    cudaGetSymbolAddress((void**)&qhi,  g_qhi);
    cudaGetSymbolAddress((void**)&qlo,  g_qlo);
    cudaGetSymbolAddress((void**)&khi,  g_khi);
    cudaGetSymbolAddress((void**)&klo,  g_klo);
    cudaGetSymbolAddress((void**)&vhi,  g_vhi);
    cudaGetSymbolAddress((void**)&vlo,  g_vlo);
    cudaGetSymbolAddress((void**)&atthi,g_atthi);
    cudaGetSymbolAddress((void**)&attlo,g_attlo);

    cudaFuncSetAttribute(gemm_mma<true,  true>,
                         cudaFuncAttributeMaxDynamicSharedMemorySize, GEMM_SMEM_BYTES);
    cudaFuncSetAttribute(gemm_mma<false, true>,
                         cudaFuncAttributeMaxDynamicSharedMemorySize, GEMM_SMEM_BYTES);
    cudaFuncSetAttribute(gemm_mma<false, false>,
                         cudaFuncAttributeMaxDynamicSharedMemorySize, GEMM_SMEM_BYTES);
    cudaFuncSetAttribute(flash_mma,
                         cudaFuncAttributeMaxDynamicSharedMemorySize, FLASH_SMEM);

    const float qscale = 0.08838834764831844f;   // 1/sqrt(128)
    int n4x = S_LEN * DIM / 4;

    split_kernel<<<(n4x + 255) / 256, 256>>>(x, xhi, xlo, n4x);
    transpose_split_kernel<<<dim3(DIM / 32,   DIM / 32), 256>>>(wq, wqth, wqtl, DIM, DIM);
    transpose_split_kernel<<<dim3(KVDIM / 32, DIM / 32), 256>>>(wk, wkth, wktl, DIM, KVDIM);
    transpose_split_kernel<<<dim3(KVDIM / 32, DIM / 32), 256>>>(wv, wvth, wvtl, DIM, KVDIM);
    transpose_split_kernel<<<dim3(DIM / 32,   DIM / 32), 256>>>(wo, woth, wotl, DIM, DIM);

    gemm_mma<true, true><<<dim3(DIM / 128, S_LEN / 128), 256, GEMM_SMEM_BYTES>>>(
        xhi, xlo, wqth, wqtl, nullptr, qhi, qlo, DIM, fcos, fsin, qscale);
    gemm_mma<true, true><<<dim3(KVDIM / 128, S_LEN / 128), 256, GEMM_SMEM_BYTES>>>(
        xhi, xlo, wkth, wktl, nullptr, khi, klo, KVDIM, fcos, fsin, 1.0f);
    gemm_mma<false, true><<<dim3(KVDIM / 128, S_LEN / 128), 256, GEMM_SMEM_BYTES>>>(
        xhi, xlo, wvth, wvtl, nullptr, vhi, vlo, KVDIM, nullptr, nullptr, 1.0f);

    flash_mma<<<dim3(S_LEN / 128, NH), 256, FLASH_SMEM>>>(
        qhi, qlo, khi, klo, vhi, vlo, atthi, attlo);

    gemm_mma<false, false><<<dim3(DIM / 128, S_LEN / 128), 256, GEMM_SMEM_BYTES>>>(
        atthi, attlo, woth, wotl, out, nullptr, nullptr, DIM, nullptr, nullptr, 1.0f);
}

// round 8
// speedup vs baseline: 5.2942x; 1.0688x over previous
#include <cuda_runtime.h>
#include <cuda_bf16.h>
#include <math.h>
#include <stdint.h>

#define DIM   4096
#define S_LEN 2048
#define HD    128
#define NH    32
#define NKV   8
#define KVDIM (NKV*HD)   // 1024
#define KTOT  4096
#define NK    (KTOT/32)  // 128
#define NQKV  (DIM + 2*KVDIM)   // 6144

// ======================= scratch globals ===================================
__device__ __nv_bfloat16 g_xhi [S_LEN * DIM];
__device__ __nv_bfloat16 g_xlo [S_LEN * DIM];
__device__ __nv_bfloat16 g_wqkvt_hi[NQKV * KTOT];   // rows: wq^T | wk^T | wv^T
__device__ __nv_bfloat16 g_wqkvt_lo[NQKV * KTOT];
__device__ __nv_bfloat16 g_wot_hi[DIM * DIM];
__device__ __nv_bfloat16 g_wot_lo[DIM * DIM];
__device__ __nv_bfloat16 g_qhi [S_LEN * DIM];
__device__ __nv_bfloat16 g_qlo [S_LEN * DIM];
__device__ __nv_bfloat16 g_khi [S_LEN * KVDIM];
__device__ __nv_bfloat16 g_klo [S_LEN * KVDIM];
__device__ __nv_bfloat16 g_vhi [S_LEN * KVDIM];
__device__ __nv_bfloat16 g_vlo [S_LEN * KVDIM];
__device__ __nv_bfloat16 g_atthi[S_LEN * DIM];
__device__ __nv_bfloat16 g_attlo[S_LEN * DIM];

// ======================= asm helpers (sm_100-safe) =========================
__device__ __forceinline__ uint32_t smem_u32(const void* p) {
    uint32_t a;
    asm("{ .reg .u64 t; cvta.to.shared.u64 t, %1; cvt.u32.u64 %0, t; }"
        : "=r"(a) : "l"(p));
    return a;
}
#define CP_ASYNC16(dst, src) \
    asm volatile("cp.async.cg.shared.global [%0], [%1], 16;" :: "r"(dst), "l"(src))
#define CP_COMMIT()  asm volatile("cp.async.commit_group;" ::: "memory")
#define CP_WAIT0()   asm volatile("cp.async.wait_group 0;"  ::: "memory")
#define CP_WAIT1()   asm volatile("cp.async.wait_group 1;"  ::: "memory")

__device__ __forceinline__ void ldsm_x4(uint32_t* r, uint32_t addr) {
    asm volatile("ldmatrix.sync.aligned.m8n8.x4.shared.b16 {%0,%1,%2,%3}, [%4];"
                 : "=r"(r[0]), "=r"(r[1]), "=r"(r[2]), "=r"(r[3]) : "r"(addr));
}
__device__ __forceinline__ void ldsm_x2(uint32_t* r, uint32_t addr) {
    asm volatile("ldmatrix.sync.aligned.m8n8.x2.shared.b16 {%0,%1}, [%2];"
                 : "=r"(r[0]), "=r"(r[1]) : "r"(addr));
}
__device__ __forceinline__ void ldsm_x2t(uint32_t* r, uint32_t addr) {
    asm volatile("ldmatrix.sync.aligned.m8n8.x2.trans.shared.b16 {%0,%1}, [%2];"
                 : "=r"(r[0]), "=r"(r[1]) : "r"(addr));
}
__device__ __forceinline__ void mma16816(float* c, const uint32_t* a, const uint32_t* b) {
    asm volatile("mma.sync.aligned.m16n8k16.row.col.f32.bf16.bf16.f32 "
                 "{%0,%1,%2,%3}, {%4,%5,%6,%7}, {%8,%9}, {%0,%1,%2,%3};"
                 : "+f"(c[0]), "+f"(c[1]), "+f"(c[2]), "+f"(c[3])
                 : "r"(a[0]), "r"(a[1]), "r"(a[2]), "r"(a[3]), "r"(b[0]), "r"(b[1]));
}
__device__ __forceinline__ uint32_t pack_bf16(float a, float b) {
    __nv_bfloat162 h = __floats2bfloat162_rn(a, b);
    return *(uint32_t*)&h;
}

// ======================= conversion kernels ================================
__global__ __launch_bounds__(256)
void split_kernel(const float* __restrict__ in, __nv_bfloat16* __restrict__ hi,
                  __nv_bfloat16* __restrict__ lo, int n4)
{
    int i = blockIdx.x * blockDim.x + threadIdx.x;
    if (i >= n4) return;
    float4 v = ((const float4*)in)[i];
    __nv_bfloat16 h0 = __float2bfloat16(v.x), h1 = __float2bfloat16(v.y);
    __nv_bfloat16 h2 = __float2bfloat16(v.z), h3 = __float2bfloat16(v.w);
    __nv_bfloat16 l0 = __float2bfloat16(v.x - __bfloat162float(h0));
    __nv_bfloat16 l1 = __float2bfloat16(v.y - __bfloat162float(h1));
    __nv_bfloat16 l2 = __float2bfloat16(v.z - __bfloat162float(h2));
    __nv_bfloat16 l3 = __float2bfloat16(v.w - __bfloat162float(h3));
    ushort4 hv = make_ushort4(*(unsigned short*)&h0, *(unsigned short*)&h1,
                              *(unsigned short*)&h2, *(unsigned short*)&h3);
    ushort4 lv = make_ushort4(*(unsigned short*)&l0, *(unsigned short*)&l1,
                              *(unsigned short*)&l2, *(unsigned short*)&l3);
    ((ushort4*)hi)[i] = hv;
    ((ushort4*)lo)[i] = lv;
}

// W[K][N] fp32 -> Thi/Tlo[N][K] bf16 (transpose + split); caller offsets T base.
__global__ __launch_bounds__(256)
void transpose_split_kernel(const float* __restrict__ W, __nv_bfloat16* __restrict__ Thi,
                            __nv_bfloat16* __restrict__ Tlo, int K, int N)
{
    __shared__ float t[32][33];
    int n0 = blockIdx.x * 32, k0 = blockIdx.y * 32;
    int tx = threadIdx.x & 31, ty = threadIdx.x >> 5;
#pragma unroll
    for (int i = 0; i < 4; i++)
        t[ty + i * 8][tx] = W[(size_t)(k0 + ty + i * 8) * N + n0 + tx];
    __syncthreads();
#pragma unroll
    for (int i = 0; i < 4; i++) {
        float a = t[tx][ty + i * 8];
        __nv_bfloat16 h = __float2bfloat16(a);
        __nv_bfloat16 l = __float2bfloat16(a - __bfloat162float(h));
        size_t o = (size_t)(n0 + ty + i * 8) * K + k0 + tx;
        Thi[o] = h; Tlo[o] = l;
    }
}

// ======================= mma.sync GEMM =====================================
// BM=BN=128, BK=32, 256 thr, warps 4x2, warp tile 32x64, x4 B-frag loads.
// MODE 0: fp32 C out (O projection).  MODE 1: fused QKV with per-CTA region
// dispatch (Q: rope+scale, K: rope, V: plain) writing bf16 hi/lo outputs.
#define GEMM_SMEM_BYTES 81920

template<int MODE>
__global__ __launch_bounds__(256, 2)
void gemm_mma(const __nv_bfloat16* __restrict__ Ahi, const __nv_bfloat16* __restrict__ Alo,
              const __nv_bfloat16* __restrict__ Bhi, const __nv_bfloat16* __restrict__ Blo,
              float* __restrict__ C,
              const float* __restrict__ fcos, const float* __restrict__ fsin)
{
    extern __shared__ char smem[];
    const uint32_t sbase = smem_u32(smem);
    const int tid  = threadIdx.x;
    const int lane = tid & 31;
    const int wid  = tid >> 5;
    const int wm   = wid & 3;
    const int wn   = wid >> 2;
    const int rowBase = blockIdx.y * 128;
    const int colBase = blockIdx.x * 128;

    auto prefetch = [&](int buf, int k0) {
#pragma unroll
        for (int s = 0; s < 2; s++) {
            const __nv_bfloat16* srcA = s ? Alo : Ahi;
            const __nv_bfloat16* srcB = s ? Blo : Bhi;
            uint32_t aB = sbase + (uint32_t)(buf * 2 + s) * 10240u;
            uint32_t bB = aB + 40960u;
#pragma unroll
            for (int c = 0; c < 2; c++) {
                int ch  = tid + c * 256;
                int row = ch >> 2;
                int kc  = (ch & 3) * 8;
                CP_ASYNC16(aB + (uint32_t)(row * 40 + kc) * 2,
                           srcA + (size_t)(rowBase + row) * KTOT + k0 + kc);
                CP_ASYNC16(bB + (uint32_t)(row * 40 + kc) * 2,
                           srcB + (size_t)(colBase + row) * KTOT + k0 + kc);
            }
        }
        CP_COMMIT();
    };

    float acc[2][8][4];
#pragma unroll
    for (int mi = 0; mi < 2; mi++)
#pragma unroll
        for (int ni = 0; ni < 8; ni++)
#pragma unroll
            for (int r = 0; r < 4; r++) acc[mi][ni][r] = 0.0f;

    const int am  = (lane & 7) + ((lane >> 3) & 1) * 8;   // A x4 row
    const int ak  = (lane >> 4) * 8;                      // A x4 k-offset
    const int bn4 = (lane & 7) + ((lane >> 4) & 1) * 8;   // B x4 row (2 n8 tiles)
    const int bk4 = ((lane >> 3) & 1) * 8;                // B x4 k-offset

    prefetch(0, 0);

    for (int i = 0; i < NK; i++) {
        CP_WAIT0();
        __syncthreads();
        if (i + 1 < NK) prefetch((i + 1) & 1, (i + 1) * 32);

        const int buf = i & 1;
        const uint32_t aHiB = sbase + (uint32_t)(buf * 2 + 0) * 10240u;
        const uint32_t aLoB = sbase + (uint32_t)(buf * 2 + 1) * 10240u;
        const uint32_t bHiB = aHiB + 40960u;
        const uint32_t bLoB = aLoB + 40960u;

#pragma unroll
        for (int ks = 0; ks < 32; ks += 16) {
            uint32_t aHi[2][4], aLo[2][4];
#pragma unroll
            for (int mi = 0; mi < 2; mi++) {
                uint32_t off = (uint32_t)((wm * 32 + mi * 16 + am) * 40 + ks + ak) * 2;
                ldsm_x4(aHi[mi], aHiB + off);
                ldsm_x4(aLo[mi], aLoB + off);
            }
#pragma unroll
            for (int ni2 = 0; ni2 < 4; ni2++) {
                uint32_t boff = (uint32_t)((wn * 64 + ni2 * 16 + bn4) * 40 + ks + bk4) * 2;
                uint32_t bh[4];
                ldsm_x4(bh, bHiB + boff);
#pragma unroll
                for (int mi = 0; mi < 2; mi++) {
                    mma16816(acc[mi][2 * ni2],     aHi[mi], bh);
                    mma16816(acc[mi][2 * ni2 + 1], aHi[mi], bh + 2);
                    mma16816(acc[mi][2 * ni2],     aLo[mi], bh);
                    mma16816(acc[mi][2 * ni2 + 1], aLo[mi], bh + 2);
                }
                uint32_t bl[4];
                ldsm_x4(bl, bLoB + boff);
#pragma unroll
                for (int mi = 0; mi < 2; mi++) {
                    mma16816(acc[mi][2 * ni2],     aHi[mi], bl);
                    mma16816(acc[mi][2 * ni2 + 1], aHi[mi], bl + 2);
                }
            }
        }
        __syncthreads();
    }

    // ---- epilogue ----
    const int qrow = lane >> 2;
    const int qcol = (lane & 3) * 2;

    __nv_bfloat16 *Chi = nullptr, *Clo = nullptr;
    int Nout = DIM, colOff = colBase;
    bool rope = false;
    float osc = 1.0f;
    if (MODE == 1) {
        if (colBase < DIM) {
            Chi = g_qhi; Clo = g_qlo; Nout = DIM; colOff = colBase;
            rope = true; osc = 0.08838834764831844f;     // 1/sqrt(128)
        } else if (colBase < DIM + KVDIM) {
            Chi = g_khi; Clo = g_klo; Nout = KVDIM; colOff = colBase - DIM;
            rope = true;
        } else {
            Chi = g_vhi; Clo = g_vlo; Nout = KVDIM; colOff = colBase - DIM - KVDIM;
        }
    }

#pragma unroll
    for (int mi = 0; mi < 2; mi++) {
#pragma unroll
        for (int half = 0; half < 2; half++) {
            int r = rowBase + wm * 32 + mi * 16 + qrow + half * 8;
#pragma unroll
            for (int ni = 0; ni < 8; ni++) {
                int n_g = colOff + wn * 64 + ni * 8 + qcol;
                float c0 = acc[mi][ni][half * 2];
                float c1 = acc[mi][ni][half * 2 + 1];
                float ox, oy;
                if (MODE == 1 && rope) {
                    int d = (n_g & (HD - 1)) >> 1;
                    float fc = fcos[r * (HD / 2) + d];
                    float fs = fsin[r * (HD / 2) + d];
                    ox = c0 * fc - c1 * fs;
                    oy = c0 * fs + c1 * fc;
                } else {
                    ox = c0; oy = c1;
                }
                if (MODE == 1) {
                    ox *= osc; oy *= osc;
                    __nv_bfloat16 h0 = __float2bfloat16(ox);
                    __nv_bfloat16 h1 = __float2bfloat16(oy);
                    float l0f = ox - __bfloat162float(h0);
                    float l1f = oy - __bfloat162float(h1);
                    size_t o = (size_t)r * Nout + n_g;
                    *(uint32_t*)&Chi[o] = pack_bf16(__bfloat162float(h0), __bfloat162float(h1));
                    *(uint32_t*)&Clo[o] = pack_bf16(l0f, l1f);
                } else {
                    *(float2*)&C[(size_t)r * DIM + n_g] = make_float2(ox, oy);
                }
            }
        }
    }
}

// ======================= flash attention (mma.sync) ========================
#define FPAD 136
#define FQ_BYTES   (128 * FPAD * 2)
#define FT_BYTES   (64 * FPAD * 2)
#define FKV_BYTES  (4 * FT_BYTES)
#define FLASH_SMEM (2 * FQ_BYTES + 2 * FKV_BYTES)   // 208896

__global__ __launch_bounds__(256, 1)
void flash_mma(const __nv_bfloat16* __restrict__ qhi, const __nv_bfloat16* __restrict__ qlo,
               const __nv_bfloat16* __restrict__ khi, const __nv_bfloat16* __restrict__ klo,
               const __nv_bfloat16* __restrict__ vhi, const __nv_bfloat16* __restrict__ vlo,
               __nv_bfloat16* __restrict__ atthi, __nv_bfloat16* __restrict__ attlo)
{
    extern __shared__ char smem[];
    const uint32_t sbase = smem_u32(smem);
    const int tid  = threadIdx.x;
    const int lane = tid & 31;
    const int w    = tid >> 5;
    const int qt   = gridDim.x - 1 - blockIdx.x;
    const int head = blockIdx.y;
    const int kvh  = head >> 2;
    const int qbase = qt * 128;
    const int ktmax = 2 * qt + 1;

    const uint32_t QHI = sbase;
    const uint32_t QLO = sbase + FQ_BYTES;
    const uint32_t KVB = sbase + 2 * FQ_BYTES;

#pragma unroll
    for (int t = 0; t < 16; t++) {
        int c = tid + t * 256;
        int arr = c >> 11;
        int rem = c & 2047;
        int row = rem >> 4;
        int ch  = rem & 15;
        const __nv_bfloat16* src = arr ? qlo : qhi;
        uint32_t dst = (arr ? QLO : QHI) + (uint32_t)(row * FPAD + ch * 8) * 2;
        CP_ASYNC16(dst, src + (size_t)(qbase + row) * DIM + head * HD + ch * 8);
    }
    auto load_kv = [&](int buf, int kt) {
        const int kbase = kt * 64;
        uint32_t base = KVB + (uint32_t)buf * FKV_BYTES;
#pragma unroll
        for (int t = 0; t < 16; t++) {
            int c = tid + t * 256;
            int arr = c >> 10;
            int rem = c & 1023;
            int row = rem >> 4;
            int ch  = rem & 15;
            const __nv_bfloat16* src = (arr == 0) ? khi : (arr == 1) ? klo
                                     : (arr == 2) ? vhi : vlo;
            uint32_t dst = base + (uint32_t)arr * FT_BYTES + (uint32_t)(row * FPAD + ch * 8) * 2;
            CP_ASYNC16(dst, src + (size_t)(kbase + row) * KVDIM + kvh * HD + ch * 8);
        }
        CP_COMMIT();
    };
    load_kv(0, 0);

    const int am = (lane & 7) + ((lane >> 3) & 1) * 8;
    const int ak = (lane >> 4) * 8;
    const int bn = lane & 7;
    const int bk = ((lane >> 3) & 1) * 8;
    const int vk = lane & 15;
    const int qrow = lane >> 2;
    const int qcol = (lane & 3) * 2;

    float O[16][4];
#pragma unroll
    for (int ni = 0; ni < 16; ni++)
#pragma unroll
        for (int r = 0; r < 4; r++) O[ni][r] = 0.0f;
    float m0 = -1e30f, m1 = -1e30f, l0 = 0.0f, l1 = 0.0f;

    for (int kt = 0; kt <= ktmax; kt++) {
        bool pf = (kt + 1 <= ktmax);
        if (pf) load_kv((kt + 1) & 1, kt + 1);
        if (pf) { CP_WAIT1(); } else { CP_WAIT0(); }
        __syncthreads();

        const uint32_t base = KVB + (uint32_t)(kt & 1) * FKV_BYTES;
        const uint32_t KHI = base, KLO = base + FT_BYTES;
        const uint32_t VHI = base + 2 * FT_BYTES, VLO = base + 3 * FT_BYTES;

        float S[8][4];
#pragma unroll
        for (int j = 0; j < 8; j++)
#pragma unroll
            for (int r = 0; r < 4; r++) S[j][r] = 0.0f;

#pragma unroll
        for (int ks = 0; ks < 8; ks++) {
            uint32_t qh[4], ql[4];
            uint32_t qoff = (uint32_t)((w * 16 + am) * FPAD + ks * 16 + ak) * 2;
            ldsm_x4(qh, QHI + qoff);
            ldsm_x4(ql, QLO + qoff);
#pragma unroll
            for (int j = 0; j < 8; j++) {
                uint32_t kh[2], kl[2];
                uint32_t koff = (uint32_t)((j * 8 + bn) * FPAD + ks * 16 + bk) * 2;
                ldsm_x2(kh, KHI + koff);
                ldsm_x2(kl, KLO + koff);
                mma16816(S[j], qh, kh);
                mma16816(S[j], ql, kh);
                mma16816(S[j], qh, kl);
            }
        }

        if (kt >= 2 * qt) {
            const int kbase = kt * 64;
            int gq0 = qbase + w * 16 + qrow;
            int gq1 = gq0 + 8;
#pragma unroll
            for (int j = 0; j < 8; j++) {
                int gk = kbase + j * 8 + qcol;
                if (gk     > gq0) S[j][0] = -1e30f;
                if (gk + 1 > gq0) S[j][1] = -1e30f;
                if (gk     > gq1) S[j][2] = -1e30f;
                if (gk + 1 > gq1) S[j][3] = -1e30f;
            }
        }

        float mx0 = -1e30f, mx1 = -1e30f;
#pragma unroll
        for (int j = 0; j < 8; j++) {
            mx0 = fmaxf(mx0, fmaxf(S[j][0], S[j][1]));
            mx1 = fmaxf(mx1, fmaxf(S[j][2], S[j][3]));
        }
        mx0 = fmaxf(mx0, __shfl_xor_sync(0xffffffffu, mx0, 1));
        mx0 = fmaxf(mx0, __shfl_xor_sync(0xffffffffu, mx0, 2));
        mx1 = fmaxf(mx1, __shfl_xor_sync(0xffffffffu, mx1, 1));
        mx1 = fmaxf(mx1, __shfl_xor_sync(0xffffffffu, mx1, 2));

        float m0n = fmaxf(m0, mx0), m1n = fmaxf(m1, mx1);
        float a0 = __expf(m0 - m0n), a1 = __expf(m1 - m1n);
        float s0 = 0.0f, s1 = 0.0f;
#pragma unroll
        for (int j = 0; j < 8; j++) {
            S[j][0] = __expf(S[j][0] - m0n);
            S[j][1] = __expf(S[j][1] - m0n);
            S[j][2] = __expf(S[j][2] - m1n);
            S[j][3] = __expf(S[j][3] - m1n);
            s0 += S[j][0] + S[j][1];
            s1 += S[j][2] + S[j][3];
        }
        s0 += __shfl_xor_sync(0xffffffffu, s0, 1);
        s0 += __shfl_xor_sync(0xffffffffu, s0, 2);
        s1 += __shfl_xor_sync(0xffffffffu, s1, 1);
        s1 += __shfl_xor_sync(0xffffffffu, s1, 2);
        l0 = l0 * a0 + s0;  m0 = m0n;
        l1 = l1 * a1 + s1;  m1 = m1n;
#pragma unroll
        for (int ni = 0; ni < 16; ni++) {
            O[ni][0] *= a0; O[ni][1] *= a0;
            O[ni][2] *= a1; O[ni][3] *= a1;
        }

#pragma unroll
        for (int kt2 = 0; kt2 < 4; kt2++) {
            uint32_t ph[4], pl[4];
#pragma unroll
            for (int half = 0; half < 2; half++) {
                float p0 = S[2 * kt2 + half][0], p1 = S[2 * kt2 + half][1];
                float p2 = S[2 * kt2 + half][2], p3 = S[2 * kt2 + half][3];
                float h0 = __bfloat162float(__float2bfloat16(p0));
                float h1 = __bfloat162float(__float2bfloat16(p1));
                float h2 = __bfloat162float(__float2bfloat16(p2));
                float h3 = __bfloat162float(__float2bfloat16(p3));
                ph[half * 2 + 0] = pack_bf16(h0, h1);
                ph[half * 2 + 1] = pack_bf16(h2, h3);
                pl[half * 2 + 0] = pack_bf16(p0 - h0, p1 - h1);
                pl[half * 2 + 1] = pack_bf16(p2 - h2, p3 - h3);
            }
#pragma unroll
            for (int ni = 0; ni < 16; ni++) {
                uint32_t vh[2], vl[2];
                uint32_t voff = (uint32_t)((kt2 * 16 + vk) * FPAD + ni * 8) * 2;
                ldsm_x2t(vh, VHI + voff);
                ldsm_x2t(vl, VLO + voff);
                mma16816(O[ni], ph, vh);
                mma16816(O[ni], pl, vh);
                mma16816(O[ni], ph, vl);
            }
        }
        __syncthreads();
    }

    float inv0 = 1.0f / l0, inv1 = 1.0f / l1;
    int gq0 = qbase + w * 16 + qrow;
    int gq1 = gq0 + 8;
#pragma unroll
    for (int ni = 0; ni < 16; ni++) {
        int col = head * HD + ni * 8 + qcol;
        float o0 = O[ni][0] * inv0, o1 = O[ni][1] * inv0;
        float o2 = O[ni][2] * inv1, o3 = O[ni][3] * inv1;
        float h0 = __bfloat162float(__float2bfloat16(o0));
        float h1 = __bfloat162float(__float2bfloat16(o1));
        float h2 = __bfloat162float(__float2bfloat16(o2));
        float h3 = __bfloat162float(__float2bfloat16(o3));
        size_t p0 = (size_t)gq0 * DIM + col;
        size_t p1 = (size_t)gq1 * DIM + col;
        *(uint32_t*)&atthi[p0] = pack_bf16(h0, h1);
        *(uint32_t*)&attlo[p0] = pack_bf16(o0 - h0, o1 - h1);
        *(uint32_t*)&atthi[p1] = pack_bf16(h2, h3);
        *(uint32_t*)&attlo[p1] = pack_bf16(o2 - h2, o3 - h3);
    }
}

// ======================= launch ============================================
extern "C" void kernel_launch(void* const* d_in, const int* in_sizes, int n_in,
                              void* d_out, int out_size)
{
    const float* x    = (const float*)d_in[0];
    const float* wq   = (const float*)d_in[1];
    const float* wk   = (const float*)d_in[2];
    const float* wv   = (const float*)d_in[3];
    const float* wo   = (const float*)d_in[4];
    const float* fcos = (const float*)d_in[5];
    const float* fsin = (const float*)d_in[6];
    float* out = (float*)d_out;

    __nv_bfloat16 *xhi, *xlo, *wqkvth, *wqkvtl, *woth, *wotl;
    __nv_bfloat16 *qhi, *qlo, *khi, *klo, *vhi, *vlo, *atthi, *attlo;
    cudaGetSymbolAddress((void**)&xhi,   g_xhi);
    cudaGetSymbolAddress((void**)&xlo,   g_xlo);
    cudaGetSymbolAddress((void**)&wqkvth,g_wqkvt_hi);
    cudaGetSymbolAddress((void**)&wqkvtl,g_wqkvt_lo);
    cudaGetSymbolAddress((void**)&woth,  g_wot_hi);
    cudaGetSymbolAddress((void**)&wotl,  g_wot_lo);
    cudaGetSymbolAddress((void**)&qhi,   g_qhi);
    cudaGetSymbolAddress((void**)&qlo,   g_qlo);
    cudaGetSymbolAddress((void**)&khi,   g_khi);
    cudaGetSymbolAddress((void**)&klo,   g_klo);
    cudaGetSymbolAddress((void**)&vhi,   g_vhi);
    cudaGetSymbolAddress((void**)&vlo,   g_vlo);
    cudaGetSymbolAddress((void**)&atthi, g_atthi);
    cudaGetSymbolAddress((void**)&attlo, g_attlo);

    cudaFuncSetAttribute(gemm_mma<0>,
                         cudaFuncAttributeMaxDynamicSharedMemorySize, GEMM_SMEM_BYTES);
    cudaFuncSetAttribute(gemm_mma<1>,
                         cudaFuncAttributeMaxDynamicSharedMemorySize, GEMM_SMEM_BYTES);
    cudaFuncSetAttribute(flash_mma,
                         cudaFuncAttributeMaxDynamicSharedMemorySize, FLASH_SMEM);

    int n4x = S_LEN * DIM / 4;

    split_kernel<<<(n4x + 255) / 256, 256>>>(x, xhi, xlo, n4x);
    // concatenated W_qkv^T: rows [0,4096) = wq^T, [4096,5120) = wk^T, [5120,6144) = wv^T
    transpose_split_kernel<<<dim3(DIM / 32,   DIM / 32), 256>>>(
        wq, wqkvth, wqkvtl, KTOT, DIM);
    transpose_split_kernel<<<dim3(KVDIM / 32, DIM / 32), 256>>>(
        wk, wqkvth + (size_t)DIM * KTOT, wqkvtl + (size_t)DIM * KTOT, KTOT, KVDIM);
    transpose_split_kernel<<<dim3(KVDIM / 32, DIM / 32), 256>>>(
        wv, wqkvth + (size_t)(DIM + KVDIM) * KTOT, wqkvtl + (size_t)(DIM + KVDIM) * KTOT,
        KTOT, KVDIM);
    transpose_split_kernel<<<dim3(DIM / 32,   DIM / 32), 256>>>(wo, woth, wotl, KTOT, DIM);

    // fused QKV projection (rope/scale/split in epilogue)
    gemm_mma<1><<<dim3(NQKV / 128, S_LEN / 128), 256, GEMM_SMEM_BYTES>>>(
        xhi, xlo, wqkvth, wqkvtl, nullptr, fcos, fsin);

    flash_mma<<<dim3(S_LEN / 128, NH), 256, FLASH_SMEM>>>(
        qhi, qlo, khi, klo, vhi, vlo, atthi, attlo);

    gemm_mma<0><<<dim3(DIM / 128, S_LEN / 128), 256, GEMM_SMEM_BYTES>>>(
        atthi, attlo, woth, wotl, out, nullptr, nullptr);
}

// round 9
// speedup vs baseline: 5.3492x; 1.0104x over previous
#include <cuda_runtime.h>
#include <cuda_bf16.h>
#include <math.h>
#include <stdint.h>

#define DIM   4096
#define S_LEN 2048
#define HD    128
#define NH    32
#define NKV   8
#define KVDIM (NKV*HD)   // 1024
#define KTOT  4096
#define NK    (KTOT/32)  // 128
#define NQKV  (DIM + 2*KVDIM)   // 6144

// ======================= scratch globals ===================================
__device__ __nv_bfloat16 g_xhi [S_LEN * DIM];
__device__ __nv_bfloat16 g_xlo [S_LEN * DIM];
__device__ __nv_bfloat16 g_wqkvt_hi[NQKV * KTOT];   // rows: wq^T | wk^T | wv^T
__device__ __nv_bfloat16 g_wqkvt_lo[NQKV * KTOT];
__device__ __nv_bfloat16 g_wot_hi[DIM * DIM];
__device__ __nv_bfloat16 g_wot_lo[DIM * DIM];
__device__ __nv_bfloat16 g_qhi [S_LEN * DIM];
__device__ __nv_bfloat16 g_qlo [S_LEN * DIM];
__device__ __nv_bfloat16 g_khi [S_LEN * KVDIM];
__device__ __nv_bfloat16 g_klo [S_LEN * KVDIM];
__device__ __nv_bfloat16 g_vhi [S_LEN * KVDIM];
__device__ __nv_bfloat16 g_vlo [S_LEN * KVDIM];
__device__ __nv_bfloat16 g_atthi[S_LEN * DIM];
__device__ __nv_bfloat16 g_attlo[S_LEN * DIM];

// ======================= asm helpers (sm_100-safe) =========================
__device__ __forceinline__ uint32_t smem_u32(const void* p) {
    uint32_t a;
    asm("{ .reg .u64 t; cvta.to.shared.u64 t, %1; cvt.u32.u64 %0, t; }"
        : "=r"(a) : "l"(p));
    return a;
}
#define CP_ASYNC16(dst, src) \
    asm volatile("cp.async.cg.shared.global [%0], [%1], 16;" :: "r"(dst), "l"(src))
#define CP_COMMIT()  asm volatile("cp.async.commit_group;" ::: "memory")
#define CP_WAIT0()   asm volatile("cp.async.wait_group 0;"  ::: "memory")

__device__ __forceinline__ void ldsm_x4(uint32_t* r, uint32_t addr) {
    asm volatile("ldmatrix.sync.aligned.m8n8.x4.shared.b16 {%0,%1,%2,%3}, [%4];"
                 : "=r"(r[0]), "=r"(r[1]), "=r"(r[2]), "=r"(r[3]) : "r"(addr));
}
__device__ __forceinline__ void ldsm_x4t(uint32_t* r, uint32_t addr) {
    asm volatile("ldmatrix.sync.aligned.m8n8.x4.trans.shared.b16 {%0,%1,%2,%3}, [%4];"
                 : "=r"(r[0]), "=r"(r[1]), "=r"(r[2]), "=r"(r[3]) : "r"(addr));
}
__device__ __forceinline__ void mma16816(float* c, const uint32_t* a, const uint32_t* b) {
    asm volatile("mma.sync.aligned.m16n8k16.row.col.f32.bf16.bf16.f32 "
                 "{%0,%1,%2,%3}, {%4,%5,%6,%7}, {%8,%9}, {%0,%1,%2,%3};"
                 : "+f"(c[0]), "+f"(c[1]), "+f"(c[2]), "+f"(c[3])
                 : "r"(a[0]), "r"(a[1]), "r"(a[2]), "r"(a[3]), "r"(b[0]), "r"(b[1]));
}
__device__ __forceinline__ uint32_t pack_bf16(float a, float b) {
    __nv_bfloat162 h = __floats2bfloat162_rn(a, b);
    return *(uint32_t*)&h;
}

// ======================= conversion kernels ================================
__global__ __launch_bounds__(256)
void split_kernel(const float* __restrict__ in, __nv_bfloat16* __restrict__ hi,
                  __nv_bfloat16* __restrict__ lo, int n4)
{
    int i = blockIdx.x * blockDim.x + threadIdx.x;
    if (i >= n4) return;
    float4 v = ((const float4*)in)[i];
    __nv_bfloat16 h0 = __float2bfloat16(v.x), h1 = __float2bfloat16(v.y);
    __nv_bfloat16 h2 = __float2bfloat16(v.z), h3 = __float2bfloat16(v.w);
    __nv_bfloat16 l0 = __float2bfloat16(v.x - __bfloat162float(h0));
    __nv_bfloat16 l1 = __float2bfloat16(v.y - __bfloat162float(h1));
    __nv_bfloat16 l2 = __float2bfloat16(v.z - __bfloat162float(h2));
    __nv_bfloat16 l3 = __float2bfloat16(v.w - __bfloat162float(h3));
    ushort4 hv = make_ushort4(*(unsigned short*)&h0, *(unsigned short*)&h1,
                              *(unsigned short*)&h2, *(unsigned short*)&h3);
    ushort4 lv = make_ushort4(*(unsigned short*)&l0, *(unsigned short*)&l1,
                              *(unsigned short*)&l2, *(unsigned short*)&l3);
    ((ushort4*)hi)[i] = hv;
    ((ushort4*)lo)[i] = lv;
}

// W[K][N] fp32 -> Thi/Tlo[N][K] bf16 (transpose + split); caller offsets T base.
__global__ __launch_bounds__(256)
void transpose_split_kernel(const float* __restrict__ W, __nv_bfloat16* __restrict__ Thi,
                            __nv_bfloat16* __restrict__ Tlo, int K, int N)
{
    __shared__ float t[32][33];
    int n0 = blockIdx.x * 32, k0 = blockIdx.y * 32;
    int tx = threadIdx.x & 31, ty = threadIdx.x >> 5;
#pragma unroll
    for (int i = 0; i < 4; i++)
        t[ty + i * 8][tx] = W[(size_t)(k0 + ty + i * 8) * N + n0 + tx];
    __syncthreads();
#pragma unroll
    for (int i = 0; i < 4; i++) {
        float a = t[tx][ty + i * 8];
        __nv_bfloat16 h = __float2bfloat16(a);
        __nv_bfloat16 l = __float2bfloat16(a - __bfloat162float(h));
        size_t o = (size_t)(n0 + ty + i * 8) * K + k0 + tx;
        Thi[o] = h; Tlo[o] = l;
    }
}

// ======================= mma.sync GEMM =====================================
// BM=BN=128, BK=32, 256 thr, warps 4x2, warp tile 32x64, x4 B-frag loads.
// MODE 0: fp32 C out (O projection).  MODE 1: fused QKV, per-CTA dispatch.
#define GEMM_SMEM_BYTES 81920

template<int MODE>
__global__ __launch_bounds__(256, 2)
void gemm_mma(const __nv_bfloat16* __restrict__ Ahi, const __nv_bfloat16* __restrict__ Alo,
              const __nv_bfloat16* __restrict__ Bhi, const __nv_bfloat16* __restrict__ Blo,
              float* __restrict__ C,
              const float* __restrict__ fcos, const float* __restrict__ fsin)
{
    extern __shared__ char smem[];
    const uint32_t sbase = smem_u32(smem);
    const int tid  = threadIdx.x;
    const int lane = tid & 31;
    const int wid  = tid >> 5;
    const int wm   = wid & 3;
    const int wn   = wid >> 2;
    const int rowBase = blockIdx.y * 128;
    const int colBase = blockIdx.x * 128;

    auto prefetch = [&](int buf, int k0) {
#pragma unroll
        for (int s = 0; s < 2; s++) {
            const __nv_bfloat16* srcA = s ? Alo : Ahi;
            const __nv_bfloat16* srcB = s ? Blo : Bhi;
            uint32_t aB = sbase + (uint32_t)(buf * 2 + s) * 10240u;
            uint32_t bB = aB + 40960u;
#pragma unroll
            for (int c = 0; c < 2; c++) {
                int ch  = tid + c * 256;
                int row = ch >> 2;
                int kc  = (ch & 3) * 8;
                CP_ASYNC16(aB + (uint32_t)(row * 40 + kc) * 2,
                           srcA + (size_t)(rowBase + row) * KTOT + k0 + kc);
                CP_ASYNC16(bB + (uint32_t)(row * 40 + kc) * 2,
                           srcB + (size_t)(colBase + row) * KTOT + k0 + kc);
            }
        }
        CP_COMMIT();
    };

    float acc[2][8][4];
#pragma unroll
    for (int mi = 0; mi < 2; mi++)
#pragma unroll
        for (int ni = 0; ni < 8; ni++)
#pragma unroll
            for (int r = 0; r < 4; r++) acc[mi][ni][r] = 0.0f;

    const int am  = (lane & 7) + ((lane >> 3) & 1) * 8;
    const int ak  = (lane >> 4) * 8;
    const int bn4 = (lane & 7) + ((lane >> 4) & 1) * 8;
    const int bk4 = ((lane >> 3) & 1) * 8;

    prefetch(0, 0);

    for (int i = 0; i < NK; i++) {
        CP_WAIT0();
        __syncthreads();
        if (i + 1 < NK) prefetch((i + 1) & 1, (i + 1) * 32);

        const int buf = i & 1;
        const uint32_t aHiB = sbase + (uint32_t)(buf * 2 + 0) * 10240u;
        const uint32_t aLoB = sbase + (uint32_t)(buf * 2 + 1) * 10240u;
        const uint32_t bHiB = aHiB + 40960u;
        const uint32_t bLoB = aLoB + 40960u;

#pragma unroll
        for (int ks = 0; ks < 32; ks += 16) {
            uint32_t aHi[2][4], aLo[2][4];
#pragma unroll
            for (int mi = 0; mi < 2; mi++) {
                uint32_t off = (uint32_t)((wm * 32 + mi * 16 + am) * 40 + ks + ak) * 2;
                ldsm_x4(aHi[mi], aHiB + off);
                ldsm_x4(aLo[mi], aLoB + off);
            }
#pragma unroll
            for (int ni2 = 0; ni2 < 4; ni2++) {
                uint32_t boff = (uint32_t)((wn * 64 + ni2 * 16 + bn4) * 40 + ks + bk4) * 2;
                uint32_t bh[4];
                ldsm_x4(bh, bHiB + boff);
#pragma unroll
                for (int mi = 0; mi < 2; mi++) {
                    mma16816(acc[mi][2 * ni2],     aHi[mi], bh);
                    mma16816(acc[mi][2 * ni2 + 1], aHi[mi], bh + 2);
                    mma16816(acc[mi][2 * ni2],     aLo[mi], bh);
                    mma16816(acc[mi][2 * ni2 + 1], aLo[mi], bh + 2);
                }
                uint32_t bl[4];
                ldsm_x4(bl, bLoB + boff);
#pragma unroll
                for (int mi = 0; mi < 2; mi++) {
                    mma16816(acc[mi][2 * ni2],     aHi[mi], bl);
                    mma16816(acc[mi][2 * ni2 + 1], aHi[mi], bl + 2);
                }
            }
        }
        // NOTE: no bottom barrier — next iteration's top barrier (after
        // CP_WAIT0) already orders buffer reuse across warps.
    }

    // ---- epilogue ----
    const int qrow = lane >> 2;
    const int qcol = (lane & 3) * 2;

    __nv_bfloat16 *Chi = nullptr, *Clo = nullptr;
    int Nout = DIM, colOff = colBase;
    bool rope = false;
    float osc = 1.0f;
    if (MODE == 1) {
        if (colBase < DIM) {
            Chi = g_qhi; Clo = g_qlo; Nout = DIM; colOff = colBase;
            rope = true; osc = 0.08838834764831844f;     // 1/sqrt(128)
        } else if (colBase < DIM + KVDIM) {
            Chi = g_khi; Clo = g_klo; Nout = KVDIM; colOff = colBase - DIM;
            rope = true;
        } else {
            Chi = g_vhi; Clo = g_vlo; Nout = KVDIM; colOff = colBase - DIM - KVDIM;
        }
    }

#pragma unroll
    for (int mi = 0; mi < 2; mi++) {
#pragma unroll
        for (int half = 0; half < 2; half++) {
            int r = rowBase + wm * 32 + mi * 16 + qrow + half * 8;
#pragma unroll
            for (int ni = 0; ni < 8; ni++) {
                int n_g = colOff + wn * 64 + ni * 8 + qcol;
                float c0 = acc[mi][ni][half * 2];
                float c1 = acc[mi][ni][half * 2 + 1];
                float ox, oy;
                if (MODE == 1 && rope) {
                    int d = (n_g & (HD - 1)) >> 1;
                    float fc = fcos[r * (HD / 2) + d];
                    float fs = fsin[r * (HD / 2) + d];
                    ox = c0 * fc - c1 * fs;
                    oy = c0 * fs + c1 * fc;
                } else {
                    ox = c0; oy = c1;
                }
                if (MODE == 1) {
                    ox *= osc; oy *= osc;
                    __nv_bfloat16 h0 = __float2bfloat16(ox);
                    __nv_bfloat16 h1 = __float2bfloat16(oy);
                    float l0f = ox - __bfloat162float(h0);
                    float l1f = oy - __bfloat162float(h1);
                    size_t o = (size_t)r * Nout + n_g;
                    *(uint32_t*)&Chi[o] = pack_bf16(__bfloat162float(h0), __bfloat162float(h1));
                    *(uint32_t*)&Clo[o] = pack_bf16(l0f, l1f);
                } else {
                    *(float2*)&C[(size_t)r * DIM + n_g] = make_float2(ox, oy);
                }
            }
        }
    }
}

// ======================= flash attention (mma.sync) ========================
#define FPAD 136
#define FQ_BYTES   (128 * FPAD * 2)
#define FT_BYTES   (64 * FPAD * 2)
#define FKV_BYTES  (4 * FT_BYTES)
#define FLASH_SMEM (2 * FQ_BYTES + 2 * FKV_BYTES)   // 208896

__global__ __launch_bounds__(256, 1)
void flash_mma(const __nv_bfloat16* __restrict__ qhi, const __nv_bfloat16* __restrict__ qlo,
               const __nv_bfloat16* __restrict__ khi, const __nv_bfloat16* __restrict__ klo,
               const __nv_bfloat16* __restrict__ vhi, const __nv_bfloat16* __restrict__ vlo,
               __nv_bfloat16* __restrict__ atthi, __nv_bfloat16* __restrict__ attlo)
{
    extern __shared__ char smem[];
    const uint32_t sbase = smem_u32(smem);
    const int tid  = threadIdx.x;
    const int lane = tid & 31;
    const int w    = tid >> 5;
    const int qt   = gridDim.x - 1 - blockIdx.x;
    const int head = blockIdx.y;
    const int kvh  = head >> 2;
    const int qbase = qt * 128;
    const int ktmax = 2 * qt + 1;

    const uint32_t QHI = sbase;
    const uint32_t QLO = sbase + FQ_BYTES;
    const uint32_t KVB = sbase + 2 * FQ_BYTES;

#pragma unroll
    for (int t = 0; t < 16; t++) {
        int c = tid + t * 256;
        int arr = c >> 11;
        int rem = c & 2047;
        int row = rem >> 4;
        int ch  = rem & 15;
        const __nv_bfloat16* src = arr ? qlo : qhi;
        uint32_t dst = (arr ? QLO : QHI) + (uint32_t)(row * FPAD + ch * 8) * 2;
        CP_ASYNC16(dst, src + (size_t)(qbase + row) * DIM + head * HD + ch * 8);
    }
    auto load_kv = [&](int buf, int kt) {
        const int kbase = kt * 64;
        uint32_t base = KVB + (uint32_t)buf * FKV_BYTES;
#pragma unroll
        for (int t = 0; t < 16; t++) {
            int c = tid + t * 256;
            int arr = c >> 10;
            int rem = c & 1023;
            int row = rem >> 4;
            int ch  = rem & 15;
            const __nv_bfloat16* src = (arr == 0) ? khi : (arr == 1) ? klo
                                     : (arr == 2) ? vhi : vlo;
            uint32_t dst = base + (uint32_t)arr * FT_BYTES + (uint32_t)(row * FPAD + ch * 8) * 2;
            CP_ASYNC16(dst, src + (size_t)(kbase + row) * KVDIM + kvh * HD + ch * 8);
        }
        CP_COMMIT();
    };
    load_kv(0, 0);   // one commit covering Q + tile 0

    const int am  = (lane & 7) + ((lane >> 3) & 1) * 8;
    const int ak  = (lane >> 4) * 8;
    const int kn4 = (lane & 7) + ((lane >> 4) & 1) * 8;   // K x4: row in n16
    const int kk4 = ((lane >> 3) & 1) * 8;                // K x4: k offset
    const int vrow = ((lane >> 3) & 1) * 8 + (lane & 7);  // V x4t: k row
    const int vcol = ((lane >> 4) & 1) * 8;               // V x4t: d col select
    const int qrow = lane >> 2;
    const int qcol = (lane & 3) * 2;

    float O[16][4];
#pragma unroll
    for (int ni = 0; ni < 16; ni++)
#pragma unroll
        for (int r = 0; r < 4; r++) O[ni][r] = 0.0f;
    float m0 = -1e30f, m1 = -1e30f, l0 = 0.0f, l1 = 0.0f;

    for (int kt = 0; kt <= ktmax; kt++) {
        CP_WAIT0();
        __syncthreads();
        if (kt + 1 <= ktmax) load_kv((kt + 1) & 1, kt + 1);

        const uint32_t base = KVB + (uint32_t)(kt & 1) * FKV_BYTES;
        const uint32_t KHI = base, KLO = base + FT_BYTES;
        const uint32_t VHI = base + 2 * FT_BYTES, VLO = base + 3 * FT_BYTES;

        // ---- S = Q K^T (3-product split), K frags via x4 ----
        float S[8][4];
#pragma unroll
        for (int j = 0; j < 8; j++)
#pragma unroll
            for (int r = 0; r < 4; r++) S[j][r] = 0.0f;

#pragma unroll
        for (int ks = 0; ks < 8; ks++) {
            uint32_t qh[4], ql[4];
            uint32_t qoff = (uint32_t)((w * 16 + am) * FPAD + ks * 16 + ak) * 2;
            ldsm_x4(qh, QHI + qoff);
            ldsm_x4(ql, QLO + qoff);
#pragma unroll
            for (int jp = 0; jp < 4; jp++) {
                uint32_t koff = (uint32_t)((jp * 16 + kn4) * FPAD + ks * 16 + kk4) * 2;
                uint32_t kh[4], kl[4];
                ldsm_x4(kh, KHI + koff);
                ldsm_x4(kl, KLO + koff);
                mma16816(S[2 * jp],     qh, kh);
                mma16816(S[2 * jp + 1], qh, kh + 2);
                mma16816(S[2 * jp],     ql, kh);
                mma16816(S[2 * jp + 1], ql, kh + 2);
                mma16816(S[2 * jp],     qh, kl);
                mma16816(S[2 * jp + 1], qh, kl + 2);
            }
        }

        if (kt >= 2 * qt) {
            const int kbase = kt * 64;
            int gq0 = qbase + w * 16 + qrow;
            int gq1 = gq0 + 8;
#pragma unroll
            for (int j = 0; j < 8; j++) {
                int gk = kbase + j * 8 + qcol;
                if (gk     > gq0) S[j][0] = -1e30f;
                if (gk + 1 > gq0) S[j][1] = -1e30f;
                if (gk     > gq1) S[j][2] = -1e30f;
                if (gk + 1 > gq1) S[j][3] = -1e30f;
            }
        }

        float mx0 = -1e30f, mx1 = -1e30f;
#pragma unroll
        for (int j = 0; j < 8; j++) {
            mx0 = fmaxf(mx0, fmaxf(S[j][0], S[j][1]));
            mx1 = fmaxf(mx1, fmaxf(S[j][2], S[j][3]));
        }
        mx0 = fmaxf(mx0, __shfl_xor_sync(0xffffffffu, mx0, 1));
        mx0 = fmaxf(mx0, __shfl_xor_sync(0xffffffffu, mx0, 2));
        mx1 = fmaxf(mx1, __shfl_xor_sync(0xffffffffu, mx1, 1));
        mx1 = fmaxf(mx1, __shfl_xor_sync(0xffffffffu, mx1, 2));

        float m0n = fmaxf(m0, mx0), m1n = fmaxf(m1, mx1);
        float a0 = __expf(m0 - m0n), a1 = __expf(m1 - m1n);
        float s0 = 0.0f, s1 = 0.0f;
#pragma unroll
        for (int j = 0; j < 8; j++) {
            S[j][0] = __expf(S[j][0] - m0n);
            S[j][1] = __expf(S[j][1] - m0n);
            S[j][2] = __expf(S[j][2] - m1n);
            S[j][3] = __expf(S[j][3] - m1n);
            s0 += S[j][0] + S[j][1];
            s1 += S[j][2] + S[j][3];
        }
        s0 += __shfl_xor_sync(0xffffffffu, s0, 1);
        s0 += __shfl_xor_sync(0xffffffffu, s0, 2);
        s1 += __shfl_xor_sync(0xffffffffu, s1, 1);
        s1 += __shfl_xor_sync(0xffffffffu, s1, 2);
        l0 = l0 * a0 + s0;  m0 = m0n;
        l1 = l1 * a1 + s1;  m1 = m1n;
#pragma unroll
        for (int ni = 0; ni < 16; ni++) {
            O[ni][0] *= a0; O[ni][1] *= a0;
            O[ni][2] *= a1; O[ni][3] *= a1;
        }

        // ---- O += P V (3-product split), V frags via x4 trans ----
#pragma unroll
        for (int kt2 = 0; kt2 < 4; kt2++) {
            uint32_t ph[4], pl[4];
#pragma unroll
            for (int half = 0; half < 2; half++) {
                float p0 = S[2 * kt2 + half][0], p1 = S[2 * kt2 + half][1];
                float p2 = S[2 * kt2 + half][2], p3 = S[2 * kt2 + half][3];
                float h0 = __bfloat162float(__float2bfloat16(p0));
                float h1 = __bfloat162float(__float2bfloat16(p1));
                float h2 = __bfloat162float(__float2bfloat16(p2));
                float h3 = __bfloat162float(__float2bfloat16(p3));
                ph[half * 2 + 0] = pack_bf16(h0, h1);
                ph[half * 2 + 1] = pack_bf16(h2, h3);
                pl[half * 2 + 0] = pack_bf16(p0 - h0, p1 - h1);
                pl[half * 2 + 1] = pack_bf16(p2 - h2, p3 - h3);
            }
#pragma unroll
            for (int nip = 0; nip < 8; nip++) {
                uint32_t voff = (uint32_t)((kt2 * 16 + vrow) * FPAD + nip * 16 + vcol) * 2;
                uint32_t vh[4], vl[4];
                ldsm_x4t(vh, VHI + voff);
                ldsm_x4t(vl, VLO + voff);
                mma16816(O[2 * nip],     ph, vh);
                mma16816(O[2 * nip + 1], ph, vh + 2);
                mma16816(O[2 * nip],     pl, vh);
                mma16816(O[2 * nip + 1], pl, vh + 2);
                mma16816(O[2 * nip],     ph, vl);
                mma16816(O[2 * nip + 1], ph, vl + 2);
            }
        }
        // no bottom barrier — top barrier of next iteration orders reuse
    }

    float inv0 = 1.0f / l0, inv1 = 1.0f / l1;
    int gq0 = qbase + w * 16 + qrow;
    int gq1 = gq0 + 8;
#pragma unroll
    for (int ni = 0; ni < 16; ni++) {
        int col = head * HD + ni * 8 + qcol;
        float o0 = O[ni][0] * inv0, o1 = O[ni][1] * inv0;
        float o2 = O[ni][2] * inv1, o3 = O[ni][3] * inv1;
        float h0 = __bfloat162float(__float2bfloat16(o0));
        float h1 = __bfloat162float(__float2bfloat16(o1));
        float h2 = __bfloat162float(__float2bfloat16(o2));
        float h3 = __bfloat162float(__float2bfloat16(o3));
        size_t p0 = (size_t)gq0 * DIM + col;
        size_t p1 = (size_t)gq1 * DIM + col;
        *(uint32_t*)&atthi[p0] = pack_bf16(h0, h1);
        *(uint32_t*)&attlo[p0] = pack_bf16(o0 - h0, o1 - h1);
        *(uint32_t*)&atthi[p1] = pack_bf16(h2, h3);
        *(uint32_t*)&attlo[p1] = pack_bf16(o2 - h2, o3 - h3);
    }
}

// ======================= launch ============================================
extern "C" void kernel_launch(void* const* d_in, const int* in_sizes, int n_in,
                              void* d_out, int out_size)
{
    const float* x    = (const float*)d_in[0];
    const float* wq   = (const float*)d_in[1];
    const float* wk   = (const float*)d_in[2];
    const float* wv   = (const float*)d_in[3];
    const float* wo   = (const float*)d_in[4];
    const float* fcos = (const float*)d_in[5];
    const float* fsin = (const float*)d_in[6];
    float* out = (float*)d_out;

    __nv_bfloat16 *xhi, *xlo, *wqkvth, *wqkvtl, *woth, *wotl;
    __nv_bfloat16 *qhi, *qlo, *khi, *klo, *vhi, *vlo, *atthi, *attlo;
    cudaGetSymbolAddress((void**)&xhi,   g_xhi);
    cudaGetSymbolAddress((void**)&xlo,   g_xlo);
    cudaGetSymbolAddress((void**)&wqkvth,g_wqkvt_hi);
    cudaGetSymbolAddress((void**)&wqkvtl,g_wqkvt_lo);
    cudaGetSymbolAddress((void**)&woth,  g_wot_hi);
    cudaGetSymbolAddress((void**)&wotl,  g_wot_lo);
    cudaGetSymbolAddress((void**)&qhi,   g_qhi);
    cudaGetSymbolAddress((void**)&qlo,   g_qlo);
    cudaGetSymbolAddress((void**)&khi,   g_khi);
    cudaGetSymbolAddress((void**)&klo,   g_klo);
    cudaGetSymbolAddress((void**)&vhi,   g_vhi);
    cudaGetSymbolAddress((void**)&vlo,   g_vlo);
    cudaGetSymbolAddress((void**)&atthi, g_atthi);
    cudaGetSymbolAddress((void**)&attlo, g_attlo);

    cudaFuncSetAttribute(gemm_mma<0>,
                         cudaFuncAttributeMaxDynamicSharedMemorySize, GEMM_SMEM_BYTES);
    cudaFuncSetAttribute(gemm_mma<1>,
                         cudaFuncAttributeMaxDynamicSharedMemorySize, GEMM_SMEM_BYTES);
    cudaFuncSetAttribute(flash_mma,
                         cudaFuncAttributeMaxDynamicSharedMemorySize, FLASH_SMEM);

    int n4x = S_LEN * DIM / 4;

    split_kernel<<<(n4x + 255) / 256, 256>>>(x, xhi, xlo, n4x);
    transpose_split_kernel<<<dim3(DIM / 32,   DIM / 32), 256>>>(
        wq, wqkvth, wqkvtl, KTOT, DIM);
    transpose_split_kernel<<<dim3(KVDIM / 32, DIM / 32), 256>>>(
        wk, wqkvth + (size_t)DIM * KTOT, wqkvtl + (size_t)DIM * KTOT, KTOT, KVDIM);
    transpose_split_kernel<<<dim3(KVDIM / 32, DIM / 32), 256>>>(
        wv, wqkvth + (size_t)(DIM + KVDIM) * KTOT, wqkvtl + (size_t)(DIM + KVDIM) * KTOT,
        KTOT, KVDIM);
    transpose_split_kernel<<<dim3(DIM / 32,   DIM / 32), 256>>>(wo, woth, wotl, KTOT, DIM);

    gemm_mma<1><<<dim3(NQKV / 128, S_LEN / 128), 256, GEMM_SMEM_BYTES>>>(
        xhi, xlo, wqkvth, wqkvtl, nullptr, fcos, fsin);

    flash_mma<<<dim3(S_LEN / 128, NH), 256, FLASH_SMEM>>>(
        qhi, qlo, khi, klo, vhi, vlo, atthi, attlo);

    gemm_mma<0><<<dim3(DIM / 128, S_LEN / 128), 256, GEMM_SMEM_BYTES>>>(
        atthi, attlo, woth, wotl, out, nullptr, nullptr);
}